// round 1
// baseline (speedup 1.0000x reference)
#include <cuda_runtime.h>

#define NB 2
#define NN 2048
#define NM 2048
#define ND 1024
#define NH 16
#define NK 64
#define NV 64
#define PAD 68   // 64 + 4: keeps float4 alignment (68*4B = 272B, 16B multiple)

// Scratch (allocation-free rule: __device__ globals)
__device__ float g_Q[NB*NH*NN*NK];   // [b][h][n][k]
__device__ float g_K[NB*NM*NK];      // [b][m][k]
__device__ float g_V[NB*NM*NV];      // [b][m][v]
__device__ float g_O[NB*NN*NH*NV];   // [b][n][h][v]

// Load a 64x64 gmem tile (64 rows of stride gstride, 64 contiguous cols) into
// smem TRANSPOSED: S[col][row], row-major with PAD stride. blockDim must be 256.
__device__ __forceinline__ void load_tile_T(float* __restrict__ S,
                                            const float* __restrict__ g,
                                            int gstride) {
    int t = threadIdx.x;
#pragma unroll
    for (int r4 = 0; r4 < 4; r4++) {
        int i   = t + r4 * 256;        // 0..1023 float4 index
        int row = i >> 4;              // 16 float4 per row
        int c4  = (i & 15) << 2;
        float4 v = *(const float4*)(g + (size_t)row * gstride + c4);
        S[(c4+0)*PAD + row] = v.x;
        S[(c4+1)*PAD + row] = v.y;
        S[(c4+2)*PAD + row] = v.z;
        S[(c4+3)*PAD + row] = v.w;
    }
}

// Same, but direct layout S[row][col].
__device__ __forceinline__ void load_tile_D(float* __restrict__ S,
                                            const float* __restrict__ g,
                                            int gstride) {
    int t = threadIdx.x;
#pragma unroll
    for (int r4 = 0; r4 < 4; r4++) {
        int i   = t + r4 * 256;
        int row = i >> 4;
        int c4  = (i & 15) << 2;
        *(float4*)(S + row*PAD + c4) = *(const float4*)(g + (size_t)row * gstride + c4);
    }
}

// ---------------------------------------------------------------------------
// Kernel 1: K = M @ P_k, V = M @ P_v   (shared M tile, two 64-wide outputs)
// grid (NM/64, NB), block 256
// ---------------------------------------------------------------------------
__global__ void __launch_bounds__(256, 2)
kv_proj_kernel(const float* __restrict__ Mi, const float* __restrict__ Pk,
               const float* __restrict__ Pv) {
    extern __shared__ float sm[];
    float* Ms = sm;              // [dd][mrow] transposed
    float* Ks = sm + 64*PAD;     // [dd][kk]
    float* Vs = sm + 2*64*PAD;   // [dd][vv]
    int b  = blockIdx.y;
    int m0 = blockIdx.x * 64;
    int tx = threadIdx.x & 15, ty = threadIdx.x >> 4;

    float ak[4][4] = {}, av[4][4] = {};
    for (int d0 = 0; d0 < ND; d0 += 64) {
        __syncthreads();
        load_tile_T(Ms, Mi + (size_t)(b*NM + m0)*ND + d0, ND);
        load_tile_D(Ks, Pk + (size_t)d0*NK, NK);
        load_tile_D(Vs, Pv + (size_t)d0*NV, NV);
        __syncthreads();
#pragma unroll 4
        for (int dd = 0; dd < 64; dd++) {
            float4 a4  = *(float4*)&Ms[dd*PAD + 4*ty];
            float4 bk4 = *(float4*)&Ks[dd*PAD + 4*tx];
            float4 bv4 = *(float4*)&Vs[dd*PAD + 4*tx];
            float a[4]  = {a4.x, a4.y, a4.z, a4.w};
            float bk[4] = {bk4.x, bk4.y, bk4.z, bk4.w};
            float bv[4] = {bv4.x, bv4.y, bv4.z, bv4.w};
#pragma unroll
            for (int i = 0; i < 4; i++)
#pragma unroll
                for (int j = 0; j < 4; j++) {
                    ak[i][j] = fmaf(a[i], bk[j], ak[i][j]);
                    av[i][j] = fmaf(a[i], bv[j], av[i][j]);
                }
        }
    }
#pragma unroll
    for (int i = 0; i < 4; i++) {
        int row = m0 + 4*ty + i;
        *(float4*)&g_K[(size_t)(b*NM + row)*NK + 4*tx] =
            make_float4(ak[i][0], ak[i][1], ak[i][2], ak[i][3]);
        *(float4*)&g_V[(size_t)(b*NM + row)*NV + 4*tx] =
            make_float4(av[i][0], av[i][1], av[i][2], av[i][3]);
    }
}

// ---------------------------------------------------------------------------
// Kernel 2: Q[b,h] = X[b] @ P_q[h]
// grid (NN/64, NH, NB), block 256
// ---------------------------------------------------------------------------
__global__ void __launch_bounds__(256, 2)
q_proj_kernel(const float* __restrict__ X, const float* __restrict__ Pq) {
    extern __shared__ float sm[];
    float* Xs = sm;             // [dd][q] transposed
    float* Bs = sm + 64*PAD;    // [dd][kk]
    int b = blockIdx.z, h = blockIdx.y, n0 = blockIdx.x * 64;
    int tx = threadIdx.x & 15, ty = threadIdx.x >> 4;

    float acc[4][4] = {};
    for (int d0 = 0; d0 < ND; d0 += 64) {
        __syncthreads();
        load_tile_T(Xs, X + (size_t)(b*NN + n0)*ND + d0, ND);
        load_tile_D(Bs, Pq + ((size_t)h*ND + d0)*NK, NK);
        __syncthreads();
#pragma unroll 4
        for (int dd = 0; dd < 64; dd++) {
            float4 a4 = *(float4*)&Xs[dd*PAD + 4*ty];
            float4 b4 = *(float4*)&Bs[dd*PAD + 4*tx];
            float a[4] = {a4.x, a4.y, a4.z, a4.w};
            float bb[4] = {b4.x, b4.y, b4.z, b4.w};
#pragma unroll
            for (int i = 0; i < 4; i++)
#pragma unroll
                for (int j = 0; j < 4; j++)
                    acc[i][j] = fmaf(a[i], bb[j], acc[i][j]);
        }
    }
#pragma unroll
    for (int i = 0; i < 4; i++) {
        size_t off = ((size_t)(b*NH + h)*NN + n0 + 4*ty + i)*NK + 4*tx;
        *(float4*)&g_Q[off] = make_float4(acc[i][0], acc[i][1], acc[i][2], acc[i][3]);
    }
}

// ---------------------------------------------------------------------------
// Kernel 3: flash attention. 64-query x 64-key tiles, online softmax,
// mask fused from gmem. grid (NN/64, NH, NB), block 256.
// ---------------------------------------------------------------------------
__global__ void __launch_bounds__(256, 2)
attn_kernel(const float* __restrict__ mask) {
    extern __shared__ float sm[];
    float* Qs = sm;              // [kk][q]   transposed
    float* Ks = sm + 64*PAD;     // [kk][key] transposed
    float* Vs = sm + 2*64*PAD;   // [key][vv] direct
    float* Ps = sm + 3*64*PAD;   // [q][key]  probabilities

    int b = blockIdx.z, h = blockIdx.y, n0 = blockIdx.x * 64;
    int tx = threadIdx.x & 15, ty = threadIdx.x >> 4;

    load_tile_T(Qs, g_Q + ((size_t)(b*NH + h)*NN + n0)*NK, NK);

    float o[4][4] = {};
    float gmax[4], gsum[4];
#pragma unroll
    for (int i = 0; i < 4; i++) { gmax[i] = -1e30f; gsum[i] = 0.0f; }

    const float* mbase = mask + ((size_t)(b*NH + h)*NN + n0) * NM;

    for (int m0 = 0; m0 < NM; m0 += 64) {
        __syncthreads();   // guards Qs on first iter; Ks/Vs/Ps reuse after
        load_tile_T(Ks, g_K + (size_t)(b*NM + m0)*NK, NK);
        load_tile_D(Vs, g_V + (size_t)(b*NM + m0)*NV, NV);
        __syncthreads();

        // S = Q @ K^T  (4x4 per thread: rows q=4ty.., cols key=4tx..)
        float s[4][4] = {};
#pragma unroll 4
        for (int kk = 0; kk < 64; kk++) {
            float4 a4 = *(float4*)&Qs[kk*PAD + 4*ty];
            float4 b4 = *(float4*)&Ks[kk*PAD + 4*tx];
            float a[4] = {a4.x, a4.y, a4.z, a4.w};
            float bb[4] = {b4.x, b4.y, b4.z, b4.w};
#pragma unroll
            for (int i = 0; i < 4; i++)
#pragma unroll
                for (int j = 0; j < 4; j++)
                    s[i][j] = fmaf(a[i], bb[j], s[i][j]);
        }

        // + mask, per-row max (reduce across the 16 tx threads via shfl)
        float rmax[4];
#pragma unroll
        for (int i = 0; i < 4; i++) {
            float4 mv = *(const float4*)(mbase + (size_t)(4*ty + i)*NM + m0 + 4*tx);
            s[i][0] += mv.x; s[i][1] += mv.y; s[i][2] += mv.z; s[i][3] += mv.w;
            rmax[i] = fmaxf(fmaxf(s[i][0], s[i][1]), fmaxf(s[i][2], s[i][3]));
        }
#pragma unroll
        for (int w = 1; w < 16; w <<= 1)
#pragma unroll
            for (int i = 0; i < 4; i++)
                rmax[i] = fmaxf(rmax[i], __shfl_xor_sync(0xffffffffu, rmax[i], w));

        // online softmax update
#pragma unroll
        for (int i = 0; i < 4; i++) {
            float mn = fmaxf(gmax[i], rmax[i]);
            float sc = __expf(gmax[i] - mn);
            gmax[i] = mn;
            float rs = 0.0f;
#pragma unroll
            for (int j = 0; j < 4; j++) {
                s[i][j] = __expf(s[i][j] - mn);
                rs += s[i][j];
            }
#pragma unroll
            for (int w = 1; w < 16; w <<= 1)
                rs += __shfl_xor_sync(0xffffffffu, rs, w);
            gsum[i] = gsum[i] * sc + rs;
#pragma unroll
            for (int j = 0; j < 4; j++) o[i][j] *= sc;
            // stash P into smem [q][key] (float4, conflict-free across tx)
            *(float4*)&Ps[(4*ty + i)*PAD + 4*tx] =
                make_float4(s[i][0], s[i][1], s[i][2], s[i][3]);
        }
        __syncthreads();

        // O += P @ V  (contraction over key; a = broadcast, b = float4)
#pragma unroll 4
        for (int key = 0; key < 64; key++) {
            float4 b4 = *(float4*)&Vs[key*PAD + 4*tx];
            float bb[4] = {b4.x, b4.y, b4.z, b4.w};
            float a[4];
#pragma unroll
            for (int i = 0; i < 4; i++) a[i] = Ps[(4*ty + i)*PAD + key];
#pragma unroll
            for (int i = 0; i < 4; i++)
#pragma unroll
                for (int j = 0; j < 4; j++)
                    o[i][j] = fmaf(a[i], bb[j], o[i][j]);
        }
    }

    // normalize + write O as [b][n][h][v]
#pragma unroll
    for (int i = 0; i < 4; i++) {
        float inv = 1.0f / gsum[i];
        size_t off = ((size_t)(b*NN + n0 + 4*ty + i)*NH + h)*NV + 4*tx;
        *(float4*)&g_O[off] = make_float4(o[i][0]*inv, o[i][1]*inv, o[i][2]*inv, o[i][3]*inv);
    }
}

// ---------------------------------------------------------------------------
// Kernel 4: Y[b,n,d] = sum_{h,v} O[b,n,h,v] * P_o[h,d,v]
// grid (ND/64, NN/64, NB), block 256. Contraction chunked per head (64 v's).
// ---------------------------------------------------------------------------
__global__ void __launch_bounds__(256, 2)
out_proj_kernel(const float* __restrict__ Po, float* __restrict__ Y) {
    extern __shared__ float sm[];
    float* Os = sm;             // [v][q]  transposed
    float* Ws = sm + 64*PAD;    // [v][dd] transposed
    int b = blockIdx.z, n0 = blockIdx.y * 64, d0 = blockIdx.x * 64;
    int tx = threadIdx.x & 15, ty = threadIdx.x >> 4;

    float acc[4][4] = {};
    for (int h = 0; h < NH; h++) {
        __syncthreads();
        load_tile_T(Os, g_O + ((size_t)(b*NN + n0)*NH + h)*NV, NH*NV);
        load_tile_T(Ws, Po + ((size_t)h*ND + d0)*NV, NV);
        __syncthreads();
#pragma unroll 4
        for (int v = 0; v < 64; v++) {
            float4 a4 = *(float4*)&Os[v*PAD + 4*ty];
            float4 b4 = *(float4*)&Ws[v*PAD + 4*tx];
            float a[4] = {a4.x, a4.y, a4.z, a4.w};
            float bb[4] = {b4.x, b4.y, b4.z, b4.w};
#pragma unroll
            for (int i = 0; i < 4; i++)
#pragma unroll
                for (int j = 0; j < 4; j++)
                    acc[i][j] = fmaf(a[i], bb[j], acc[i][j]);
        }
    }
#pragma unroll
    for (int i = 0; i < 4; i++) {
        size_t off = ((size_t)(b*NN + n0 + 4*ty + i))*ND + d0 + 4*tx;
        *(float4*)&Y[off] = make_float4(acc[i][0], acc[i][1], acc[i][2], acc[i][3]);
    }
}

// ---------------------------------------------------------------------------
extern "C" void kernel_launch(void* const* d_in, const int* in_sizes, int n_in,
                              void* d_out, int out_size) {
    const float* X    = (const float*)d_in[0];
    const float* Mi   = (const float*)d_in[1];
    const float* mask = (const float*)d_in[2];
    const float* Pq   = (const float*)d_in[3];
    const float* Pk   = (const float*)d_in[4];
    const float* Pv   = (const float*)d_in[5];
    const float* Po   = (const float*)d_in[6];
    float* Y = (float*)d_out;

    int smem2 = 2 * 64 * PAD * 4;   // 34,816 B
    int smem3 = 3 * 64 * PAD * 4;   // 52,224 B
    int smem4 = 4 * 64 * PAD * 4;   // 69,632 B
    cudaFuncSetAttribute(kv_proj_kernel,  cudaFuncAttributeMaxDynamicSharedMemorySize, smem3);
    cudaFuncSetAttribute(q_proj_kernel,   cudaFuncAttributeMaxDynamicSharedMemorySize, smem2);
    cudaFuncSetAttribute(attn_kernel,     cudaFuncAttributeMaxDynamicSharedMemorySize, smem4);
    cudaFuncSetAttribute(out_proj_kernel, cudaFuncAttributeMaxDynamicSharedMemorySize, smem2);

    kv_proj_kernel<<<dim3(NM/64, NB), 256, smem3>>>(Mi, Pk, Pv);
    q_proj_kernel<<<dim3(NN/64, NH, NB), 256, smem2>>>(X, Pq);
    attn_kernel<<<dim3(NN/64, NH, NB), 256, smem4>>>(mask);
    out_proj_kernel<<<dim3(ND/64, NN/64, NB), 256, smem2>>>(Po, Y);
}

// round 6
// speedup vs baseline: 1.6037x; 1.6037x over previous
#include <cuda_runtime.h>
#include <cuda_fp16.h>
#include <cstdint>

#define NB 2
#define NN 2048
#define NM 2048
#define ND 1024
#define NH 16
#define NK 64
#define NV 64
#define PAD 68

// ---------------- scratch (__device__ globals; no allocs allowed) ----------
__device__ float  g_O[(size_t)NB*NN*NH*NV];            // [b][n][h][v] fp32
__device__ __half g_Qh[(size_t)NB*NH*NN*NK];           // [b][h][n][k]
__device__ __half g_Ql[(size_t)NB*NH*NN*NK];
__device__ __half g_Kh[(size_t)NB*NM*NK];              // [b][m][k]
__device__ __half g_Kl[(size_t)NB*NM*NK];
__device__ __half g_Vh[(size_t)NB*NM*NV];              // [b][m][v]
__device__ __half g_Vl[(size_t)NB*NM*NV];

// ---------------- helpers --------------------------------------------------
__device__ __forceinline__ uint32_t smem_u32(const void* p) {
    uint32_t a;
    asm("{ .reg .u64 t; cvta.to.shared.u64 t, %1; cvt.u32.u64 %0, t; }" : "=r"(a) : "l"(p));
    return a;
}
__device__ __forceinline__ void ldsm_x4(uint32_t (&r)[4], uint32_t a) {
    asm volatile("ldmatrix.sync.aligned.m8n8.x4.shared.b16 {%0,%1,%2,%3}, [%4];"
                 : "=r"(r[0]), "=r"(r[1]), "=r"(r[2]), "=r"(r[3]) : "r"(a));
}
__device__ __forceinline__ void ldsm_x2(uint32_t& r0, uint32_t& r1, uint32_t a) {
    asm volatile("ldmatrix.sync.aligned.m8n8.x2.shared.b16 {%0,%1}, [%2];"
                 : "=r"(r0), "=r"(r1) : "r"(a));
}
__device__ __forceinline__ void ldsm_x2t(uint32_t& r0, uint32_t& r1, uint32_t a) {
    asm volatile("ldmatrix.sync.aligned.m8n8.x2.trans.shared.b16 {%0,%1}, [%2];"
                 : "=r"(r0), "=r"(r1) : "r"(a));
}
__device__ __forceinline__ void mma16816(float (&c)[4], const uint32_t (&a)[4],
                                         uint32_t b0, uint32_t b1) {
    asm volatile("mma.sync.aligned.m16n8k16.row.col.f32.f16.f16.f32 "
                 "{%0,%1,%2,%3}, {%4,%5,%6,%7}, {%8,%9}, {%0,%1,%2,%3};"
                 : "+f"(c[0]), "+f"(c[1]), "+f"(c[2]), "+f"(c[3])
                 : "r"(a[0]), "r"(a[1]), "r"(a[2]), "r"(a[3]), "r"(b0), "r"(b1));
}
__device__ __forceinline__ uint32_t ex2_h2(uint32_t x) {
    uint32_t r;
    asm volatile("ex2.approx.f16x2 %0, %1;" : "=r"(r) : "r"(x));
    return r;
}

// ---------------- fp32 SIMT tile loaders (projections) ---------------------
__device__ __forceinline__ void load_tile_T(float* __restrict__ S,
                                            const float* __restrict__ g, int gstride) {
    int t = threadIdx.x;
#pragma unroll
    for (int r4 = 0; r4 < 4; r4++) {
        int i = t + r4 * 256, row = i >> 4, c4 = (i & 15) << 2;
        float4 v = *(const float4*)(g + (size_t)row * gstride + c4);
        S[(c4+0)*PAD + row] = v.x; S[(c4+1)*PAD + row] = v.y;
        S[(c4+2)*PAD + row] = v.z; S[(c4+3)*PAD + row] = v.w;
    }
}
__device__ __forceinline__ void load_tile_D(float* __restrict__ S,
                                            const float* __restrict__ g, int gstride) {
    int t = threadIdx.x;
#pragma unroll
    for (int r4 = 0; r4 < 4; r4++) {
        int i = t + r4 * 256, row = i >> 4, c4 = (i & 15) << 2;
        *(float4*)(S + row*PAD + c4) = *(const float4*)(g + (size_t)row * gstride + c4);
    }
}
__device__ __forceinline__ void split_store4(const float* v, __half* hp, __half* lp) {
    __half h0 = __float2half_rn(v[0]), h1 = __float2half_rn(v[1]);
    __half h2 = __float2half_rn(v[2]), h3 = __float2half_rn(v[3]);
    *(__half2*)(hp)     = __halves2half2(h0, h1);
    *(__half2*)(hp + 2) = __halves2half2(h2, h3);
    *(__half2*)(lp)     = __halves2half2(__float2half_rn(v[0] - __half2float(h0)),
                                         __float2half_rn(v[1] - __half2float(h1)));
    *(__half2*)(lp + 2) = __halves2half2(__float2half_rn(v[2] - __half2float(h2)),
                                         __float2half_rn(v[3] - __half2float(h3)));
}

// ---------------------------------------------------------------------------
// Kernel 1: K/V projection -> fp16 splits (both row-major [b][m][*])
// ---------------------------------------------------------------------------
__global__ void __launch_bounds__(256, 2)
kv_proj_kernel(const float* __restrict__ Mi, const float* __restrict__ Pk,
               const float* __restrict__ Pv) {
    extern __shared__ float sm[];
    float* Ms = sm; float* Ks = sm + 64*PAD; float* Vs = sm + 2*64*PAD;
    int b = blockIdx.y, m0 = blockIdx.x * 64;
    int tx = threadIdx.x & 15, ty = threadIdx.x >> 4;
    float ak[4][4] = {}, av[4][4] = {};
    for (int d0 = 0; d0 < ND; d0 += 64) {
        __syncthreads();
        load_tile_T(Ms, Mi + (size_t)(b*NM + m0)*ND + d0, ND);
        load_tile_D(Ks, Pk + (size_t)d0*NK, NK);
        load_tile_D(Vs, Pv + (size_t)d0*NV, NV);
        __syncthreads();
#pragma unroll 4
        for (int dd = 0; dd < 64; dd++) {
            float4 a4 = *(float4*)&Ms[dd*PAD + 4*ty];
            float4 bk4 = *(float4*)&Ks[dd*PAD + 4*tx];
            float4 bv4 = *(float4*)&Vs[dd*PAD + 4*tx];
            float a[4] = {a4.x,a4.y,a4.z,a4.w};
            float bk[4] = {bk4.x,bk4.y,bk4.z,bk4.w};
            float bv[4] = {bv4.x,bv4.y,bv4.z,bv4.w};
#pragma unroll
            for (int i = 0; i < 4; i++)
#pragma unroll
                for (int j = 0; j < 4; j++) {
                    ak[i][j] = fmaf(a[i], bk[j], ak[i][j]);
                    av[i][j] = fmaf(a[i], bv[j], av[i][j]);
                }
        }
    }
#pragma unroll
    for (int i = 0; i < 4; i++) {
        int mrow = m0 + 4*ty + i;
        size_t ko = (size_t)(b*NM + mrow)*NK + 4*tx;
        split_store4(ak[i], &g_Kh[ko], &g_Kl[ko]);
        size_t vo = (size_t)(b*NM + mrow)*NV + 4*tx;
        split_store4(av[i], &g_Vh[vo], &g_Vl[vo]);
    }
}

// ---------------------------------------------------------------------------
// Kernel 2: Q projection (fp32 accuracy anchor) -> fp16 splits
// ---------------------------------------------------------------------------
__global__ void __launch_bounds__(256, 2)
q_proj_kernel(const float* __restrict__ X, const float* __restrict__ Pq) {
    extern __shared__ float sm[];
    float* Xs = sm; float* Bs = sm + 64*PAD;
    int b = blockIdx.z, h = blockIdx.y, n0 = blockIdx.x * 64;
    int tx = threadIdx.x & 15, ty = threadIdx.x >> 4;
    float acc[4][4] = {};
    for (int d0 = 0; d0 < ND; d0 += 64) {
        __syncthreads();
        load_tile_T(Xs, X + (size_t)(b*NN + n0)*ND + d0, ND);
        load_tile_D(Bs, Pq + ((size_t)h*ND + d0)*NK, NK);
        __syncthreads();
#pragma unroll 4
        for (int dd = 0; dd < 64; dd++) {
            float4 a4 = *(float4*)&Xs[dd*PAD + 4*ty];
            float4 b4 = *(float4*)&Bs[dd*PAD + 4*tx];
            float a[4] = {a4.x,a4.y,a4.z,a4.w};
            float bb[4] = {b4.x,b4.y,b4.z,b4.w};
#pragma unroll
            for (int i = 0; i < 4; i++)
#pragma unroll
                for (int j = 0; j < 4; j++)
                    acc[i][j] = fmaf(a[i], bb[j], acc[i][j]);
        }
    }
#pragma unroll
    for (int i = 0; i < 4; i++) {
        size_t off = ((size_t)(b*NH + h)*NN + n0 + 4*ty + i)*NK + 4*tx;
        split_store4(acc[i], &g_Qh[off], &g_Ql[off]);
    }
}

// ---------------------------------------------------------------------------
// Kernel 3: mma.sync flash attention.
//   CTA = 128 queries, 8 warps x 16 rows each, key tile 64.
//   S = QhKh + QlKh + QhKl (m16n8k16, fp32 acc), warp-private online softmax,
//   P fed to PV directly from registers (C-frag == A-frag layout),
//   O += P@Vh + P@Vl. 2 CTA/SM.
// ---------------------------------------------------------------------------
// smem byte offsets (tile rows are 128B: 64 halves)
#define S_QH 0
#define S_QL 16384
#define S_KH 32768
#define S_KL 40960
#define S_VH 49152
#define S_VL 57344
#define SMEM_ATT 65536
#define L2E 1.4426950408889634f

__device__ __forceinline__ void load_f16_tile(char* s, const __half* g,
                                              int gstride, int rows) {
    for (int i = threadIdx.x; i < rows * 8; i += 256) {
        int row = i >> 3, c = i & 7;
        uint4 v = *(const uint4*)(g + (size_t)row * gstride + c * 8);
        int off = row * 128 + c * 16;
        *(uint4*)(s + (off ^ ((off >> 3) & 0x70))) = v;
    }
}

// fragment address helpers (swizzle folded: low-7 bits of row*128 are 0)
__device__ __forceinline__ uint32_t a_addr(uint32_t base, int row0, int ks, int lane) {
    int m = lane >> 3;
    int r = row0 + ((m & 1) << 3) + (lane & 7);
    int cb = ((((m >> 1) << 3) + (ks << 4)) << 1);
    return base + r * 128 + (cb ^ ((r & 7) << 4));
}
__device__ __forceinline__ uint32_t b_addr(uint32_t base, int j, int ks, int lane) {
    int l = lane & 15;
    int r = (j << 3) + (l & 7);
    int cb = (((ks << 4) + ((l >> 3) << 3)) << 1);
    return base + r * 128 + (cb ^ ((l & 7) << 4));
}
__device__ __forceinline__ uint32_t v_addr(uint32_t base, int ks, int jv, int lane) {
    int l = lane & 15;
    int r = (ks << 4) + l;
    int cb = (jv << 4);
    return base + r * 128 + (cb ^ ((l & 7) << 4));
}

__global__ void __launch_bounds__(256, 2)
attn_kernel(const float* __restrict__ mask) {
    extern __shared__ char smem[];
    const uint32_t sb = smem_u32(smem);
    const int tid = threadIdx.x;
    const int w = tid >> 5, lane = tid & 31;
    const int gid = lane >> 2, t4 = lane & 3;
    const int wrow0 = w * 16;
    const int b = blockIdx.z, h = blockIdx.y, n0 = blockIdx.x * 128;

    // Q tiles to smem
    size_t qoff = ((size_t)(b*NH + h)*NN + n0) * NK;
    load_f16_tile(smem + S_QH, g_Qh + qoff, NK, 128);
    load_f16_tile(smem + S_QL, g_Ql + qoff, NK, 128);
    __syncthreads();

    // persistent Qh fragments (16 rows x 64k = 4 k-steps)
    uint32_t qh[4][4];
#pragma unroll
    for (int ks = 0; ks < 4; ks++) ldsm_x4(qh[ks], a_addr(sb + S_QH, wrow0, ks, lane));

    float o[8][4];
#pragma unroll
    for (int j = 0; j < 8; j++) { o[j][0]=0.f; o[j][1]=0.f; o[j][2]=0.f; o[j][3]=0.f; }
    float gmax0 = -1e30f, gmax1 = -1e30f, gs0 = 0.f, gs1 = 0.f;

    const int grow0 = n0 + wrow0 + gid;
    const float* mp0 = mask + (((size_t)(b*NH + h)*NN + grow0))*(size_t)NM + 2*t4;
    const float* mp1 = mp0 + (size_t)8 * NM;

    for (int it = 0; it < NM / 64; it++) {
        const int m0 = it * 64;
        if (it) __syncthreads();               // prior iter's smem reads done
        load_f16_tile(smem + S_KH, g_Kh + (size_t)(b*NM + m0)*NK, NK, 64);
        load_f16_tile(smem + S_KL, g_Kl + (size_t)(b*NM + m0)*NK, NK, 64);
        load_f16_tile(smem + S_VH, g_Vh + (size_t)(b*NM + m0)*NV, NV, 64);
        load_f16_tile(smem + S_VL, g_Vl + (size_t)(b*NM + m0)*NV, NV, 64);
        __syncthreads();

        // ---- S = Q K^T (3-pass split) -------------------------------------
        float c[8][4];
#pragma unroll
        for (int j = 0; j < 8; j++) { c[j][0]=0.f; c[j][1]=0.f; c[j][2]=0.f; c[j][3]=0.f; }
#pragma unroll
        for (int ks = 0; ks < 4; ks++) {
            uint32_t ql[4];
            ldsm_x4(ql, a_addr(sb + S_QL, wrow0, ks, lane));
#pragma unroll
            for (int j = 0; j < 8; j++) {
                uint32_t bh0, bh1, bl0, bl1;
                ldsm_x2(bh0, bh1, b_addr(sb + S_KH, j, ks, lane));
                mma16816(c[j], qh[ks], bh0, bh1);
                mma16816(c[j], ql, bh0, bh1);
                ldsm_x2(bl0, bl1, b_addr(sb + S_KL, j, ks, lane));
                mma16816(c[j], qh[ks], bl0, bl1);
            }
        }

        // ---- + mask, row max ---------------------------------------------
        float mx0 = -1e30f, mx1 = -1e30f;
#pragma unroll
        for (int j = 0; j < 8; j++) {
            float2 a = *(const float2*)(mp0 + m0 + 8*j);
            float2 d = *(const float2*)(mp1 + m0 + 8*j);
            c[j][0] += a.x; c[j][1] += a.y; c[j][2] += d.x; c[j][3] += d.y;
            mx0 = fmaxf(mx0, fmaxf(c[j][0], c[j][1]));
            mx1 = fmaxf(mx1, fmaxf(c[j][2], c[j][3]));
        }
        mx0 = fmaxf(mx0, __shfl_xor_sync(0xffffffffu, mx0, 1));
        mx0 = fmaxf(mx0, __shfl_xor_sync(0xffffffffu, mx0, 2));
        mx1 = fmaxf(mx1, __shfl_xor_sync(0xffffffffu, mx1, 1));
        mx1 = fmaxf(mx1, __shfl_xor_sync(0xffffffffu, mx1, 2));

        float mn0 = fmaxf(gmax0, mx0), mn1 = fmaxf(gmax1, mx1);
        float sc0 = __expf(gmax0 - mn0), sc1 = __expf(gmax1 - mn1);
        gmax0 = mn0; gmax1 = mn1;

        // ---- exp -> P (f16), row sums ------------------------------------
        uint32_t pk[8][2];
        float rs0 = 0.f, rs1 = 0.f;
#pragma unroll
        for (int j = 0; j < 8; j++) {
            __half2 t0 = __floats2half2_rn((c[j][0]-mn0)*L2E, (c[j][1]-mn0)*L2E);
            __half2 t1 = __floats2half2_rn((c[j][2]-mn1)*L2E, (c[j][3]-mn1)*L2E);
            pk[j][0] = ex2_h2(*(uint32_t*)&t0);
            pk[j][1] = ex2_h2(*(uint32_t*)&t1);
            float2 f0 = __half22float2(*(__half2*)&pk[j][0]);
            float2 f1 = __half22float2(*(__half2*)&pk[j][1]);
            rs0 += f0.x + f0.y; rs1 += f1.x + f1.y;
        }
        rs0 += __shfl_xor_sync(0xffffffffu, rs0, 1);
        rs0 += __shfl_xor_sync(0xffffffffu, rs0, 2);
        rs1 += __shfl_xor_sync(0xffffffffu, rs1, 1);
        rs1 += __shfl_xor_sync(0xffffffffu, rs1, 2);
        gs0 = gs0 * sc0 + rs0;
        gs1 = gs1 * sc1 + rs1;

        // ---- rescale O, then O += P @ (Vh + Vl) --------------------------
#pragma unroll
        for (int j = 0; j < 8; j++) {
            o[j][0] *= sc0; o[j][1] *= sc0; o[j][2] *= sc1; o[j][3] *= sc1;
        }
#pragma unroll
        for (int ks = 0; ks < 4; ks++) {
            uint32_t pa[4] = { pk[2*ks][0], pk[2*ks][1], pk[2*ks+1][0], pk[2*ks+1][1] };
#pragma unroll
            for (int jv = 0; jv < 8; jv++) {
                uint32_t v0, v1;
                ldsm_x2t(v0, v1, v_addr(sb + S_VH, ks, jv, lane));
                mma16816(o[jv], pa, v0, v1);
                ldsm_x2t(v0, v1, v_addr(sb + S_VL, ks, jv, lane));
                mma16816(o[jv], pa, v0, v1);
            }
        }
    }

    // ---- epilogue: normalize, store to g_O [b][n][h][v] -------------------
    float inv0 = 1.0f / gs0, inv1 = 1.0f / gs1;
    size_t o0 = ((size_t)(b*NN + grow0)*NH + h)*NV + 2*t4;
    size_t o1 = ((size_t)(b*NN + grow0 + 8)*NH + h)*NV + 2*t4;
#pragma unroll
    for (int jv = 0; jv < 8; jv++) {
        *(float2*)&g_O[o0 + 8*jv] = make_float2(o[jv][0]*inv0, o[jv][1]*inv0);
        *(float2*)&g_O[o1 + 8*jv] = make_float2(o[jv][2]*inv1, o[jv][3]*inv1);
    }
}

// ---------------------------------------------------------------------------
// Kernel 4: Y[b,n,d] = sum_{h,v} O[b,n,h,v] * P_o[h,d,v]   (fp32)
// ---------------------------------------------------------------------------
__global__ void __launch_bounds__(256, 2)
out_proj_kernel(const float* __restrict__ Po, float* __restrict__ Y) {
    extern __shared__ float sm[];
    float* Os = sm; float* Ws = sm + 64*PAD;
    int b = blockIdx.z, n0 = blockIdx.y * 64, d0 = blockIdx.x * 64;
    int tx = threadIdx.x & 15, ty = threadIdx.x >> 4;
    float acc[4][4] = {};
    for (int h = 0; h < NH; h++) {
        __syncthreads();
        load_tile_T(Os, g_O + ((size_t)(b*NN + n0)*NH + h)*NV, NH*NV);
        load_tile_T(Ws, Po + ((size_t)h*ND + d0)*NV, NV);
        __syncthreads();
#pragma unroll 4
        for (int v = 0; v < 64; v++) {
            float4 a4 = *(float4*)&Os[v*PAD + 4*ty];
            float4 b4 = *(float4*)&Ws[v*PAD + 4*tx];
            float a[4] = {a4.x,a4.y,a4.z,a4.w};
            float bb[4] = {b4.x,b4.y,b4.z,b4.w};
#pragma unroll
            for (int i = 0; i < 4; i++)
#pragma unroll
                for (int j = 0; j < 4; j++)
                    acc[i][j] = fmaf(a[i], bb[j], acc[i][j]);
        }
    }
#pragma unroll
    for (int i = 0; i < 4; i++) {
        size_t off = ((size_t)(b*NN + n0 + 4*ty + i))*ND + d0 + 4*tx;
        *(float4*)&Y[off] = make_float4(acc[i][0], acc[i][1], acc[i][2], acc[i][3]);
    }
}

// ---------------------------------------------------------------------------
extern "C" void kernel_launch(void* const* d_in, const int* in_sizes, int n_in,
                              void* d_out, int out_size) {
    const float* X    = (const float*)d_in[0];
    const float* Mi   = (const float*)d_in[1];
    const float* mask = (const float*)d_in[2];
    const float* Pq   = (const float*)d_in[3];
    const float* Pk   = (const float*)d_in[4];
    const float* Pv   = (const float*)d_in[5];
    const float* Po   = (const float*)d_in[6];
    float* Y = (float*)d_out;

    int smem2 = 2 * 64 * PAD * 4;
    int smem3 = 3 * 64 * PAD * 4;
    cudaFuncSetAttribute(kv_proj_kernel,  cudaFuncAttributeMaxDynamicSharedMemorySize, smem3);
    cudaFuncSetAttribute(q_proj_kernel,   cudaFuncAttributeMaxDynamicSharedMemorySize, smem2);
    cudaFuncSetAttribute(attn_kernel,     cudaFuncAttributeMaxDynamicSharedMemorySize, SMEM_ATT);
    cudaFuncSetAttribute(out_proj_kernel, cudaFuncAttributeMaxDynamicSharedMemorySize, smem2);

    kv_proj_kernel<<<dim3(NM/64, NB), 256, smem3>>>(Mi, Pk, Pv);
    q_proj_kernel<<<dim3(NN/64, NH, NB), 256, smem2>>>(X, Pq);
    attn_kernel<<<dim3(NN/128, NH, NB), 256, SMEM_ATT>>>(mask);
    out_proj_kernel<<<dim3(ND/64, NN/64, NB), 256, smem2>>>(Po, Y);
}

// round 7
// speedup vs baseline: 2.0024x; 1.2486x over previous
#include <cuda_runtime.h>
#include <cuda_fp16.h>
#include <cstdint>

#define NB 2
#define NN 2048
#define NM 2048
#define ND 1024
#define NH 16
#define NK 64
#define NV 64

// ---------------- scratch (__device__ globals; no allocs allowed) ----------
__device__ __half g_Xh[(size_t)NB*NN*ND],   g_Xl[(size_t)NB*NN*ND];
__device__ __half g_Mh[(size_t)NB*NM*ND],   g_Ml[(size_t)NB*NM*ND];
__device__ __half g_Pqh[(size_t)NH*ND*NK],  g_Pql[(size_t)NH*ND*NK];
__device__ __half g_Pkh[(size_t)ND*NK],     g_Pkl[(size_t)ND*NK];
__device__ __half g_Pvh[(size_t)ND*NV],     g_Pvl[(size_t)ND*NV];
__device__ __half g_Poh[(size_t)NH*ND*NV],  g_Pol[(size_t)NH*ND*NV];
__device__ __half g_Qh[(size_t)NB*NH*NN*NK], g_Ql[(size_t)NB*NH*NN*NK];
__device__ __half g_Kh[(size_t)NB*NM*NK],   g_Kl[(size_t)NB*NM*NK];
__device__ __half g_Vh[(size_t)NB*NM*NV],   g_Vl[(size_t)NB*NM*NV];
__device__ __half g_Oh[(size_t)NB*NN*NH*NV], g_Ol[(size_t)NB*NN*NH*NV];

// ---------------- helpers --------------------------------------------------
__device__ __forceinline__ uint32_t smem_u32(const void* p) {
    uint32_t a;
    asm("{ .reg .u64 t; cvta.to.shared.u64 t, %1; cvt.u32.u64 %0, t; }" : "=r"(a) : "l"(p));
    return a;
}
__device__ __forceinline__ void ldsm_x4(uint32_t (&r)[4], uint32_t a) {
    asm volatile("ldmatrix.sync.aligned.m8n8.x4.shared.b16 {%0,%1,%2,%3}, [%4];"
                 : "=r"(r[0]), "=r"(r[1]), "=r"(r[2]), "=r"(r[3]) : "r"(a));
}
__device__ __forceinline__ void ldsm_x2(uint32_t& r0, uint32_t& r1, uint32_t a) {
    asm volatile("ldmatrix.sync.aligned.m8n8.x2.shared.b16 {%0,%1}, [%2];"
                 : "=r"(r0), "=r"(r1) : "r"(a));
}
__device__ __forceinline__ void ldsm_x2t(uint32_t& r0, uint32_t& r1, uint32_t a) {
    asm volatile("ldmatrix.sync.aligned.m8n8.x2.trans.shared.b16 {%0,%1}, [%2];"
                 : "=r"(r0), "=r"(r1) : "r"(a));
}
__device__ __forceinline__ void mma16816(float (&c)[4], const uint32_t (&a)[4],
                                         uint32_t b0, uint32_t b1) {
    asm volatile("mma.sync.aligned.m16n8k16.row.col.f32.f16.f16.f32 "
                 "{%0,%1,%2,%3}, {%4,%5,%6,%7}, {%8,%9}, {%0,%1,%2,%3};"
                 : "+f"(c[0]), "+f"(c[1]), "+f"(c[2]), "+f"(c[3])
                 : "r"(a[0]), "r"(a[1]), "r"(a[2]), "r"(a[3]), "r"(b0), "r"(b1));
}
__device__ __forceinline__ uint32_t ex2_h2(uint32_t x) {
    uint32_t r;
    asm volatile("ex2.approx.f16x2 %0, %1;" : "=r"(r) : "r"(x));
    return r;
}
__device__ __forceinline__ void split2(float a, float b, __half* hp, __half* lp) {
    __half h0 = __float2half_rn(a), h1 = __float2half_rn(b);
    *(__half2*)hp = __halves2half2(h0, h1);
    *(__half2*)lp = __halves2half2(__float2half_rn(a - __half2float(h0)),
                                   __float2half_rn(b - __half2float(h1)));
}

// swizzled 128B-row f16 tile loader (64 halves per row)
__device__ __forceinline__ void load_f16_tile(char* s, const __half* g,
                                              int gstride, int rows) {
    for (int i = threadIdx.x; i < rows * 8; i += 256) {
        int row = i >> 3, c = i & 7;
        uint4 v = *(const uint4*)(g + (size_t)row * gstride + c * 8);
        int off = row * 128 + c * 16;
        *(uint4*)(s + (off ^ ((off >> 3) & 0x70))) = v;
    }
}
// fragment address helpers (swizzle folded)
__device__ __forceinline__ uint32_t a_addr(uint32_t base, int row0, int ks, int lane) {
    int m = lane >> 3;
    int r = row0 + ((m & 1) << 3) + (lane & 7);
    int cb = ((((m >> 1) << 3) + (ks << 4)) << 1);
    return base + r * 128 + (cb ^ ((r & 7) << 4));
}
__device__ __forceinline__ uint32_t b_addr(uint32_t base, int j, int ks, int lane) {
    int l = lane & 15;
    int r = (j << 3) + (l & 7);
    int cb = (((ks << 4) + ((l >> 3) << 3)) << 1);
    return base + r * 128 + (cb ^ ((l & 7) << 4));
}
__device__ __forceinline__ uint32_t v_addr(uint32_t base, int ks, int jv, int lane) {
    int l = lane & 15;
    int r = (ks << 4) + l;
    int cb = (jv << 4);
    return base + r * 128 + (cb ^ ((l & 7) << 4));
}

// ---------------------------------------------------------------------------
// Kernel 0: fp32 -> fp16 hi/lo split (elementwise, float4)
// ---------------------------------------------------------------------------
__global__ void split_kernel(const float* __restrict__ s, __half* __restrict__ hp,
                             __half* __restrict__ lp, int n4) {
    for (int i = blockIdx.x * blockDim.x + threadIdx.x; i < n4;
         i += gridDim.x * blockDim.x) {
        float4 v = ((const float4*)s)[i];
        split2(v.x, v.y, hp + 4*i,     lp + 4*i);
        split2(v.z, v.w, hp + 4*i + 2, lp + 4*i + 2);
    }
}

// ---------------------------------------------------------------------------
// Shared HMMA core: C[128x64] += A[128xK] @ B, 3-pass split-fp16.
// TB=true : B stored [k][n] (trans ldsm) ; TB=false: B stored [n][k].
// ---------------------------------------------------------------------------
#define G_SA_H 0
#define G_SA_L 16384
#define G_SB_H 32768
#define G_SB_L 40960
#define SMEM_G 49152

template <bool TB>
__device__ __forceinline__ void gemm128x64(const __half* Ah, const __half* Al, int lda,
                                           const __half* Bh, const __half* Bl, int ldb,
                                           size_t bstep, int nchunks, float (&c)[8][4]) {
    extern __shared__ char smem[];
    uint32_t sb = smem_u32(smem);
    int lane = threadIdx.x & 31, w = threadIdx.x >> 5, wrow0 = w * 16;
    for (int ch = 0; ch < nchunks; ch++) {
        if (ch) __syncthreads();
        load_f16_tile(smem + G_SA_H, Ah + ch * 64, lda, 128);
        load_f16_tile(smem + G_SA_L, Al + ch * 64, lda, 128);
        load_f16_tile(smem + G_SB_H, Bh + ch * bstep, ldb, 64);
        load_f16_tile(smem + G_SB_L, Bl + ch * bstep, ldb, 64);
        __syncthreads();
#pragma unroll
        for (int ks = 0; ks < 4; ks++) {
            uint32_t ah[4], al[4];
            ldsm_x4(ah, a_addr(sb + G_SA_H, wrow0, ks, lane));
            ldsm_x4(al, a_addr(sb + G_SA_L, wrow0, ks, lane));
#pragma unroll
            for (int j = 0; j < 8; j++) {
                uint32_t bh0, bh1, bl0, bl1;
                if (TB) {
                    ldsm_x2t(bh0, bh1, v_addr(sb + G_SB_H, ks, j, lane));
                    ldsm_x2t(bl0, bl1, v_addr(sb + G_SB_L, ks, j, lane));
                } else {
                    ldsm_x2(bh0, bh1, b_addr(sb + G_SB_H, j, ks, lane));
                    ldsm_x2(bl0, bl1, b_addr(sb + G_SB_L, j, ks, lane));
                }
                mma16816(c[j], ah, bh0, bh1);
                mma16816(c[j], al, bh0, bh1);
                mma16816(c[j], ah, bl0, bl1);
            }
        }
    }
}

// ---------------------------------------------------------------------------
// Kernel 1: Q projection. grid (NN/128, NH, NB)
// ---------------------------------------------------------------------------
__global__ void __launch_bounds__(256, 2)
q_proj_kernel() {
    int b = blockIdx.z, h = blockIdx.y, n0 = blockIdx.x * 128;
    float c[8][4] = {};
    gemm128x64<true>(g_Xh + (size_t)(b*NN + n0)*ND, g_Xl + (size_t)(b*NN + n0)*ND, ND,
                     g_Pqh + (size_t)h*ND*NK, g_Pql + (size_t)h*ND*NK, NK,
                     (size_t)64*NK, ND/64, c);
    int lane = threadIdx.x & 31, w = threadIdx.x >> 5;
    int gid = lane >> 2, t4 = lane & 3;
    int grow0 = n0 + w*16 + gid;
    size_t r0 = ((size_t)(b*NH + h)*NN + grow0)*NK;
#pragma unroll
    for (int j = 0; j < 8; j++) {
        int col = 8*j + 2*t4;
        split2(c[j][0], c[j][1], &g_Qh[r0 + col], &g_Ql[r0 + col]);
        split2(c[j][2], c[j][3], &g_Qh[r0 + 8*NK + col], &g_Ql[r0 + 8*NK + col]);
    }
}

// ---------------------------------------------------------------------------
// Kernel 2: K/V projection. grid (NM/128, 2(sel), NB)
// ---------------------------------------------------------------------------
__global__ void __launch_bounds__(256, 2)
kv_proj_kernel() {
    int b = blockIdx.z, sel = blockIdx.y, m0 = blockIdx.x * 128;
    const __half* Bh = sel ? g_Pvh : g_Pkh;
    const __half* Bl = sel ? g_Pvl : g_Pkl;
    float c[8][4] = {};
    gemm128x64<true>(g_Mh + (size_t)(b*NM + m0)*ND, g_Ml + (size_t)(b*NM + m0)*ND, ND,
                     Bh, Bl, NK, (size_t)64*NK, ND/64, c);
    __half* Ch = sel ? g_Vh : g_Kh;
    __half* Cl = sel ? g_Vl : g_Kl;
    int lane = threadIdx.x & 31, w = threadIdx.x >> 5;
    int gid = lane >> 2, t4 = lane & 3;
    int grow0 = m0 + w*16 + gid;
    size_t r0 = (size_t)(b*NM + grow0)*NK;
#pragma unroll
    for (int j = 0; j < 8; j++) {
        int col = 8*j + 2*t4;
        split2(c[j][0], c[j][1], &Ch[r0 + col], &Cl[r0 + col]);
        split2(c[j][2], c[j][3], &Ch[r0 + 8*NK + col], &Cl[r0 + 8*NK + col]);
    }
}

// ---------------------------------------------------------------------------
// Kernel 3: mma.sync flash attention (unchanged core; epilogue -> fp16 split O)
// ---------------------------------------------------------------------------
#define S_QH 0
#define S_QL 16384
#define S_KH 32768
#define S_KL 40960
#define S_VH 49152
#define S_VL 57344
#define SMEM_ATT 65536
#define L2E 1.4426950408889634f

__global__ void __launch_bounds__(256, 2)
attn_kernel(const float* __restrict__ mask) {
    extern __shared__ char smem[];
    const uint32_t sb = smem_u32(smem);
    const int tid = threadIdx.x;
    const int w = tid >> 5, lane = tid & 31;
    const int gid = lane >> 2, t4 = lane & 3;
    const int wrow0 = w * 16;
    const int b = blockIdx.z, h = blockIdx.y, n0 = blockIdx.x * 128;

    size_t qoff = ((size_t)(b*NH + h)*NN + n0) * NK;
    load_f16_tile(smem + S_QH, g_Qh + qoff, NK, 128);
    load_f16_tile(smem + S_QL, g_Ql + qoff, NK, 128);
    __syncthreads();

    uint32_t qh[4][4];
#pragma unroll
    for (int ks = 0; ks < 4; ks++) ldsm_x4(qh[ks], a_addr(sb + S_QH, wrow0, ks, lane));

    float o[8][4];
#pragma unroll
    for (int j = 0; j < 8; j++) { o[j][0]=0.f; o[j][1]=0.f; o[j][2]=0.f; o[j][3]=0.f; }
    float gmax0 = -1e30f, gmax1 = -1e30f, gs0 = 0.f, gs1 = 0.f;

    const int grow0 = n0 + wrow0 + gid;
    const float* mp0 = mask + (((size_t)(b*NH + h)*NN + grow0))*(size_t)NM + 2*t4;
    const float* mp1 = mp0 + (size_t)8 * NM;

    for (int it = 0; it < NM / 64; it++) {
        const int m0 = it * 64;
        if (it) __syncthreads();
        load_f16_tile(smem + S_KH, g_Kh + (size_t)(b*NM + m0)*NK, NK, 64);
        load_f16_tile(smem + S_KL, g_Kl + (size_t)(b*NM + m0)*NK, NK, 64);
        load_f16_tile(smem + S_VH, g_Vh + (size_t)(b*NM + m0)*NV, NV, 64);
        load_f16_tile(smem + S_VL, g_Vl + (size_t)(b*NM + m0)*NV, NV, 64);
        __syncthreads();

        float c[8][4];
#pragma unroll
        for (int j = 0; j < 8; j++) { c[j][0]=0.f; c[j][1]=0.f; c[j][2]=0.f; c[j][3]=0.f; }
#pragma unroll
        for (int ks = 0; ks < 4; ks++) {
            uint32_t ql[4];
            ldsm_x4(ql, a_addr(sb + S_QL, wrow0, ks, lane));
#pragma unroll
            for (int j = 0; j < 8; j++) {
                uint32_t bh0, bh1, bl0, bl1;
                ldsm_x2(bh0, bh1, b_addr(sb + S_KH, j, ks, lane));
                mma16816(c[j], qh[ks], bh0, bh1);
                mma16816(c[j], ql, bh0, bh1);
                ldsm_x2(bl0, bl1, b_addr(sb + S_KL, j, ks, lane));
                mma16816(c[j], qh[ks], bl0, bl1);
            }
        }

        float mx0 = -1e30f, mx1 = -1e30f;
#pragma unroll
        for (int j = 0; j < 8; j++) {
            float2 a = *(const float2*)(mp0 + m0 + 8*j);
            float2 d = *(const float2*)(mp1 + m0 + 8*j);
            c[j][0] += a.x; c[j][1] += a.y; c[j][2] += d.x; c[j][3] += d.y;
            mx0 = fmaxf(mx0, fmaxf(c[j][0], c[j][1]));
            mx1 = fmaxf(mx1, fmaxf(c[j][2], c[j][3]));
        }
        mx0 = fmaxf(mx0, __shfl_xor_sync(0xffffffffu, mx0, 1));
        mx0 = fmaxf(mx0, __shfl_xor_sync(0xffffffffu, mx0, 2));
        mx1 = fmaxf(mx1, __shfl_xor_sync(0xffffffffu, mx1, 1));
        mx1 = fmaxf(mx1, __shfl_xor_sync(0xffffffffu, mx1, 2));

        float mn0 = fmaxf(gmax0, mx0), mn1 = fmaxf(gmax1, mx1);
        float sc0 = __expf(gmax0 - mn0), sc1 = __expf(gmax1 - mn1);
        gmax0 = mn0; gmax1 = mn1;

        uint32_t pk[8][2];
        float rs0 = 0.f, rs1 = 0.f;
#pragma unroll
        for (int j = 0; j < 8; j++) {
            __half2 t0 = __floats2half2_rn((c[j][0]-mn0)*L2E, (c[j][1]-mn0)*L2E);
            __half2 t1 = __floats2half2_rn((c[j][2]-mn1)*L2E, (c[j][3]-mn1)*L2E);
            pk[j][0] = ex2_h2(*(uint32_t*)&t0);
            pk[j][1] = ex2_h2(*(uint32_t*)&t1);
            float2 f0 = __half22float2(*(__half2*)&pk[j][0]);
            float2 f1 = __half22float2(*(__half2*)&pk[j][1]);
            rs0 += f0.x + f0.y; rs1 += f1.x + f1.y;
        }
        rs0 += __shfl_xor_sync(0xffffffffu, rs0, 1);
        rs0 += __shfl_xor_sync(0xffffffffu, rs0, 2);
        rs1 += __shfl_xor_sync(0xffffffffu, rs1, 1);
        rs1 += __shfl_xor_sync(0xffffffffu, rs1, 2);
        gs0 = gs0 * sc0 + rs0;
        gs1 = gs1 * sc1 + rs1;

#pragma unroll
        for (int j = 0; j < 8; j++) {
            o[j][0] *= sc0; o[j][1] *= sc0; o[j][2] *= sc1; o[j][3] *= sc1;
        }
#pragma unroll
        for (int ks = 0; ks < 4; ks++) {
            uint32_t pa[4] = { pk[2*ks][0], pk[2*ks][1], pk[2*ks+1][0], pk[2*ks+1][1] };
#pragma unroll
            for (int jv = 0; jv < 8; jv++) {
                uint32_t v0, v1;
                ldsm_x2t(v0, v1, v_addr(sb + S_VH, ks, jv, lane));
                mma16816(o[jv], pa, v0, v1);
                ldsm_x2t(v0, v1, v_addr(sb + S_VL, ks, jv, lane));
                mma16816(o[jv], pa, v0, v1);
            }
        }
    }

    // epilogue: normalize, split-store O as fp16 hi/lo [b][n][h][v]
    float inv0 = 1.0f / gs0, inv1 = 1.0f / gs1;
    size_t o0 = ((size_t)(b*NN + grow0)*NH + h)*NV + 2*t4;
    size_t o1 = ((size_t)(b*NN + grow0 + 8)*NH + h)*NV + 2*t4;
#pragma unroll
    for (int jv = 0; jv < 8; jv++) {
        split2(o[jv][0]*inv0, o[jv][1]*inv0, &g_Oh[o0 + 8*jv], &g_Ol[o0 + 8*jv]);
        split2(o[jv][2]*inv1, o[jv][3]*inv1, &g_Oh[o1 + 8*jv], &g_Ol[o1 + 8*jv]);
    }
}

// ---------------------------------------------------------------------------
// Kernel 4: output projection. grid (ND/64, NN/128, NB). Contraction = 16 heads.
// ---------------------------------------------------------------------------
__global__ void __launch_bounds__(256, 2)
out_proj_kernel(float* __restrict__ Y) {
    int b = blockIdx.z, n0 = blockIdx.y * 128, d0 = blockIdx.x * 64;
    float c[8][4] = {};
    gemm128x64<false>(g_Oh + (size_t)(b*NN + n0)*(NH*NV), g_Ol + (size_t)(b*NN + n0)*(NH*NV),
                      NH*NV,
                      g_Poh + (size_t)d0*NV, g_Pol + (size_t)d0*NV, NV,
                      (size_t)ND*NV, NH, c);
    int lane = threadIdx.x & 31, w = threadIdx.x >> 5;
    int gid = lane >> 2, t4 = lane & 3;
    int grow0 = n0 + w*16 + gid;
    size_t r0 = (size_t)(b*NN + grow0)*ND + d0;
#pragma unroll
    for (int j = 0; j < 8; j++) {
        int col = 8*j + 2*t4;
        *(float2*)&Y[r0 + col]        = make_float2(c[j][0], c[j][1]);
        *(float2*)&Y[r0 + 8*ND + col] = make_float2(c[j][2], c[j][3]);
    }
}

// ---------------------------------------------------------------------------
extern "C" void kernel_launch(void* const* d_in, const int* in_sizes, int n_in,
                              void* d_out, int out_size) {
    const float* X    = (const float*)d_in[0];
    const float* Mi   = (const float*)d_in[1];
    const float* mask = (const float*)d_in[2];
    const float* Pq   = (const float*)d_in[3];
    const float* Pk   = (const float*)d_in[4];
    const float* Pv   = (const float*)d_in[5];
    const float* Po   = (const float*)d_in[6];
    float* Y = (float*)d_out;

    cudaFuncSetAttribute(q_proj_kernel,   cudaFuncAttributeMaxDynamicSharedMemorySize, SMEM_G);
    cudaFuncSetAttribute(kv_proj_kernel,  cudaFuncAttributeMaxDynamicSharedMemorySize, SMEM_G);
    cudaFuncSetAttribute(attn_kernel,     cudaFuncAttributeMaxDynamicSharedMemorySize, SMEM_ATT);
    cudaFuncSetAttribute(out_proj_kernel, cudaFuncAttributeMaxDynamicSharedMemorySize, SMEM_G);

    __half *xh, *xl, *mh, *ml, *pqh, *pql, *pkh, *pkl, *pvh, *pvl, *poh, *pol;
    cudaGetSymbolAddress((void**)&xh,  g_Xh);  cudaGetSymbolAddress((void**)&xl,  g_Xl);
    cudaGetSymbolAddress((void**)&mh,  g_Mh);  cudaGetSymbolAddress((void**)&ml,  g_Ml);
    cudaGetSymbolAddress((void**)&pqh, g_Pqh); cudaGetSymbolAddress((void**)&pql, g_Pql);
    cudaGetSymbolAddress((void**)&pkh, g_Pkh); cudaGetSymbolAddress((void**)&pkl, g_Pkl);
    cudaGetSymbolAddress((void**)&pvh, g_Pvh); cudaGetSymbolAddress((void**)&pvl, g_Pvl);
    cudaGetSymbolAddress((void**)&poh, g_Poh); cudaGetSymbolAddress((void**)&pol, g_Pol);

    auto split = [&](const float* s, __half* hp, __half* lp, size_t n) {
        int n4 = (int)(n / 4);
        int blocks = (n4 + 255) / 256; if (blocks > 4096) blocks = 4096;
        split_kernel<<<blocks, 256>>>(s, hp, lp, n4);
    };
    split(X,  xh,  xl,  (size_t)NB*NN*ND);
    split(Mi, mh,  ml,  (size_t)NB*NM*ND);
    split(Pq, pqh, pql, (size_t)NH*ND*NK);
    split(Pk, pkh, pkl, (size_t)ND*NK);
    split(Pv, pvh, pvl, (size_t)ND*NV);
    split(Po, poh, pol, (size_t)NH*ND*NV);

    kv_proj_kernel<<<dim3(NM/128, 2, NB), 256, SMEM_G>>>();
    q_proj_kernel<<<dim3(NN/128, NH, NB), 256, SMEM_G>>>();
    attn_kernel<<<dim3(NN/128, NH, NB), 256, SMEM_ATT>>>(mask);
    out_proj_kernel<<<dim3(ND/64, NN/128, NB), 256, SMEM_G>>>(Y);
}

// round 8
// speedup vs baseline: 3.3727x; 1.6843x over previous
#include <cuda_runtime.h>
#include <cuda_fp16.h>
#include <cstdint>

#define NB 2
#define NN 2048
#define NM 2048
#define ND 1024
#define NH 16
#define NK 64
#define NV 64

// ---------------- scratch (__device__ globals; no allocs allowed) ----------
__device__ __half g_Xh[(size_t)NB*NN*ND],   g_Xl[(size_t)NB*NN*ND];
__device__ __half g_Mh[(size_t)NB*NM*ND],   g_Ml[(size_t)NB*NM*ND];
__device__ __half g_Pqh[(size_t)NH*ND*NK],  g_Pql[(size_t)NH*ND*NK];
__device__ __half g_Pkh[(size_t)ND*NK],     g_Pkl[(size_t)ND*NK];
__device__ __half g_Pvh[(size_t)ND*NV],     g_Pvl[(size_t)ND*NV];
__device__ __half g_Poh[(size_t)NH*ND*NV],  g_Pol[(size_t)NH*ND*NV];
__device__ __half g_Qh[(size_t)NB*NH*NN*NK], g_Ql[(size_t)NB*NH*NN*NK];
__device__ __half g_Kh[(size_t)NB*NM*NK],   g_Kl[(size_t)NB*NM*NK];
__device__ __half g_Vh[(size_t)NB*NM*NV],   g_Vl[(size_t)NB*NM*NV];
__device__ __half g_Oh[(size_t)NB*NN*NH*NV], g_Ol[(size_t)NB*NN*NH*NV];

// ---------------- helpers --------------------------------------------------
__device__ __forceinline__ uint32_t smem_u32(const void* p) {
    uint32_t a;
    asm("{ .reg .u64 t; cvta.to.shared.u64 t, %1; cvt.u32.u64 %0, t; }" : "=r"(a) : "l"(p));
    return a;
}
__device__ __forceinline__ void ldsm_x4(uint32_t (&r)[4], uint32_t a) {
    asm volatile("ldmatrix.sync.aligned.m8n8.x4.shared.b16 {%0,%1,%2,%3}, [%4];"
                 : "=r"(r[0]), "=r"(r[1]), "=r"(r[2]), "=r"(r[3]) : "r"(a));
}
__device__ __forceinline__ void ldsm_x2(uint32_t& r0, uint32_t& r1, uint32_t a) {
    asm volatile("ldmatrix.sync.aligned.m8n8.x2.shared.b16 {%0,%1}, [%2];"
                 : "=r"(r0), "=r"(r1) : "r"(a));
}
__device__ __forceinline__ void ldsm_x2t(uint32_t& r0, uint32_t& r1, uint32_t a) {
    asm volatile("ldmatrix.sync.aligned.m8n8.x2.trans.shared.b16 {%0,%1}, [%2];"
                 : "=r"(r0), "=r"(r1) : "r"(a));
}
__device__ __forceinline__ void mma16816(float (&c)[4], const uint32_t (&a)[4],
                                         uint32_t b0, uint32_t b1) {
    asm volatile("mma.sync.aligned.m16n8k16.row.col.f32.f16.f16.f32 "
                 "{%0,%1,%2,%3}, {%4,%5,%6,%7}, {%8,%9}, {%0,%1,%2,%3};"
                 : "+f"(c[0]), "+f"(c[1]), "+f"(c[2]), "+f"(c[3])
                 : "r"(a[0]), "r"(a[1]), "r"(a[2]), "r"(a[3]), "r"(b0), "r"(b1));
}
__device__ __forceinline__ uint32_t ex2_h2(uint32_t x) {
    uint32_t r;
    asm volatile("ex2.approx.f16x2 %0, %1;" : "=r"(r) : "r"(x));
    return r;
}
__device__ __forceinline__ void split2(float a, float b, __half* hp, __half* lp) {
    __half h0 = __float2half_rn(a), h1 = __float2half_rn(b);
    *(__half2*)hp = __halves2half2(h0, h1);
    *(__half2*)lp = __halves2half2(__float2half_rn(a - __half2float(h0)),
                                   __float2half_rn(b - __half2float(h1)));
}
#define CP_COMMIT() asm volatile("cp.async.commit_group;" ::: "memory")
#define CP_WAIT1()  asm volatile("cp.async.wait_group 1;" ::: "memory")
#define CP_WAIT0()  asm volatile("cp.async.wait_group 0;" ::: "memory")

// swizzled 128B-row f16 tile loader (64 halves per row) — sync version
__device__ __forceinline__ void load_f16_tile(char* s, const __half* g,
                                              int gstride, int rows) {
    for (int i = threadIdx.x; i < rows * 8; i += 256) {
        int row = i >> 3, c = i & 7;
        uint4 v = *(const uint4*)(g + (size_t)row * gstride + c * 8);
        int off = row * 128 + c * 16;
        *(uint4*)(s + (off ^ ((off >> 3) & 0x70))) = v;
    }
}
// cp.async version
__device__ __forceinline__ void load_f16_tile_cp(uint32_t sbase, const __half* g,
                                                 int gstride, int rows) {
    for (int i = threadIdx.x; i < rows * 8; i += 256) {
        int row = i >> 3, c = i & 7;
        int off = row * 128 + c * 16;
        asm volatile("cp.async.cg.shared.global [%0], [%1], 16;"
                     :: "r"(sbase + (off ^ ((off >> 3) & 0x70))),
                        "l"(g + (size_t)row * gstride + c * 8) : "memory");
    }
}
// fragment address helpers (swizzle folded)
__device__ __forceinline__ uint32_t a_addr(uint32_t base, int row0, int ks, int lane) {
    int m = lane >> 3;
    int r = row0 + ((m & 1) << 3) + (lane & 7);
    int cb = ((((m >> 1) << 3) + (ks << 4)) << 1);
    return base + r * 128 + (cb ^ ((r & 7) << 4));
}
__device__ __forceinline__ uint32_t b_addr(uint32_t base, int j, int ks, int lane) {
    int l = lane & 15;
    int r = (j << 3) + (l & 7);
    int cb = (((ks << 4) + ((l >> 3) << 3)) << 1);
    return base + r * 128 + (cb ^ ((l & 7) << 4));
}
__device__ __forceinline__ uint32_t v_addr(uint32_t base, int ks, int jv, int lane) {
    int l = lane & 15;
    int r = (ks << 4) + l;
    int cb = (jv << 4);
    return base + r * 128 + (cb ^ ((l & 7) << 4));
}

// ---------------------------------------------------------------------------
// Kernel 0: fp32 -> fp16 hi/lo split (elementwise, float4)
// ---------------------------------------------------------------------------
__global__ void split_kernel(const float* __restrict__ s, __half* __restrict__ hp,
                             __half* __restrict__ lp, int n4) {
    for (int i = blockIdx.x * blockDim.x + threadIdx.x; i < n4;
         i += gridDim.x * blockDim.x) {
        float4 v = ((const float4*)s)[i];
        split2(v.x, v.y, hp + 4*i,     lp + 4*i);
        split2(v.z, v.w, hp + 4*i + 2, lp + 4*i + 2);
    }
}

// ---------------------------------------------------------------------------
// Shared HMMA core, 2-stage cp.async pipeline.
// Stage layout (48KB): A_H 0, A_L 16K, B_H 32K, B_L 40K. 2 stages = 96KB.
// ---------------------------------------------------------------------------
#define GST    49152
#define G_SA_H 0
#define G_SA_L 16384
#define G_SB_H 32768
#define G_SB_L 40960
#define SMEM_G 98304

template <bool TB>
__device__ __forceinline__ void gemm128x64(const __half* Ah, const __half* Al, int lda,
                                           const __half* Bh, const __half* Bl, int ldb,
                                           size_t bstep, int nchunks, float (&c)[8][4]) {
    extern __shared__ char smem[];
    uint32_t sb = smem_u32(smem);
    int lane = threadIdx.x & 31, w = threadIdx.x >> 5, wrow0 = w * 16;

    // prologue: stage 0
    {
        uint32_t st = sb;
        load_f16_tile_cp(st + G_SA_H, Ah, lda, 128);
        load_f16_tile_cp(st + G_SA_L, Al, lda, 128);
        load_f16_tile_cp(st + G_SB_H, Bh, ldb, 64);
        load_f16_tile_cp(st + G_SB_L, Bl, ldb, 64);
        CP_COMMIT();
    }
    for (int ch = 0; ch < nchunks; ch++) {
        if (ch + 1 < nchunks) {
            uint32_t st = sb + ((ch + 1) & 1) * GST;
            load_f16_tile_cp(st + G_SA_H, Ah + (ch + 1) * 64, lda, 128);
            load_f16_tile_cp(st + G_SA_L, Al + (ch + 1) * 64, lda, 128);
            load_f16_tile_cp(st + G_SB_H, Bh + (ch + 1) * bstep, ldb, 64);
            load_f16_tile_cp(st + G_SB_L, Bl + (ch + 1) * bstep, ldb, 64);
            CP_COMMIT();
            CP_WAIT1();
        } else {
            CP_WAIT0();
        }
        __syncthreads();
        uint32_t st = sb + (ch & 1) * GST;
#pragma unroll
        for (int ks = 0; ks < 4; ks++) {
            uint32_t ah[4], al[4];
            ldsm_x4(ah, a_addr(st + G_SA_H, wrow0, ks, lane));
            ldsm_x4(al, a_addr(st + G_SA_L, wrow0, ks, lane));
#pragma unroll
            for (int j = 0; j < 8; j++) {
                uint32_t bh0, bh1, bl0, bl1;
                if (TB) {
                    ldsm_x2t(bh0, bh1, v_addr(st + G_SB_H, ks, j, lane));
                    ldsm_x2t(bl0, bl1, v_addr(st + G_SB_L, ks, j, lane));
                } else {
                    ldsm_x2(bh0, bh1, b_addr(st + G_SB_H, j, ks, lane));
                    ldsm_x2(bl0, bl1, b_addr(st + G_SB_L, j, ks, lane));
                }
                mma16816(c[j], ah, bh0, bh1);
                mma16816(c[j], al, bh0, bh1);
                mma16816(c[j], ah, bl0, bl1);
            }
        }
        __syncthreads();
    }
}

// ---------------------------------------------------------------------------
// Kernel 1: Q projection. grid (NN/128, NH, NB)
// ---------------------------------------------------------------------------
__global__ void __launch_bounds__(256, 2)
q_proj_kernel() {
    int b = blockIdx.z, h = blockIdx.y, n0 = blockIdx.x * 128;
    float c[8][4] = {};
    gemm128x64<true>(g_Xh + (size_t)(b*NN + n0)*ND, g_Xl + (size_t)(b*NN + n0)*ND, ND,
                     g_Pqh + (size_t)h*ND*NK, g_Pql + (size_t)h*ND*NK, NK,
                     (size_t)64*NK, ND/64, c);
    int lane = threadIdx.x & 31, w = threadIdx.x >> 5;
    int gid = lane >> 2, t4 = lane & 3;
    int grow0 = n0 + w*16 + gid;
    size_t r0 = ((size_t)(b*NH + h)*NN + grow0)*NK;
#pragma unroll
    for (int j = 0; j < 8; j++) {
        int col = 8*j + 2*t4;
        split2(c[j][0], c[j][1], &g_Qh[r0 + col], &g_Ql[r0 + col]);
        split2(c[j][2], c[j][3], &g_Qh[r0 + 8*NK + col], &g_Ql[r0 + 8*NK + col]);
    }
}

// ---------------------------------------------------------------------------
// Kernel 2: K/V projection. grid (NM/128, 2(sel), NB)
// ---------------------------------------------------------------------------
__global__ void __launch_bounds__(256, 2)
kv_proj_kernel() {
    int b = blockIdx.z, sel = blockIdx.y, m0 = blockIdx.x * 128;
    const __half* Bh = sel ? g_Pvh : g_Pkh;
    const __half* Bl = sel ? g_Pvl : g_Pkl;
    float c[8][4] = {};
    gemm128x64<true>(g_Mh + (size_t)(b*NM + m0)*ND, g_Ml + (size_t)(b*NM + m0)*ND, ND,
                     Bh, Bl, NK, (size_t)64*NK, ND/64, c);
    __half* Ch = sel ? g_Vh : g_Kh;
    __half* Cl = sel ? g_Vl : g_Kl;
    int lane = threadIdx.x & 31, w = threadIdx.x >> 5;
    int gid = lane >> 2, t4 = lane & 3;
    int grow0 = m0 + w*16 + gid;
    size_t r0 = (size_t)(b*NM + grow0)*NK;
#pragma unroll
    for (int j = 0; j < 8; j++) {
        int col = 8*j + 2*t4;
        split2(c[j][0], c[j][1], &Ch[r0 + col], &Cl[r0 + col]);
        split2(c[j][2], c[j][3], &Ch[r0 + 8*NK + col], &Cl[r0 + 8*NK + col]);
    }
}

// ---------------------------------------------------------------------------
// Kernel 3: mma.sync flash attention, 2-stage cp.async K/V pipeline.
// Stage (32KB): KH 0, KL 8K, VH 16K, VL 24K; stages at 0, 32K.
// Persistent Q: QH 64K, QL 80K. Total 96KB.
// ---------------------------------------------------------------------------
#define AST    32768
#define A_KH   0
#define A_KL   8192
#define A_VH   16384
#define A_VL   24576
#define S_QH   65536
#define S_QL   81920
#define SMEM_ATT 98304
#define L2E 1.4426950408889634f

__global__ void __launch_bounds__(256, 2)
attn_kernel(const float* __restrict__ mask) {
    extern __shared__ char smem[];
    const uint32_t sb = smem_u32(smem);
    const int tid = threadIdx.x;
    const int w = tid >> 5, lane = tid & 31;
    const int gid = lane >> 2, t4 = lane & 3;
    const int wrow0 = w * 16;
    const int b = blockIdx.z, h = blockIdx.y, n0 = blockIdx.x * 128;

    const __half* kh_g = g_Kh + (size_t)b*NM*NK;
    const __half* kl_g = g_Kl + (size_t)b*NM*NK;
    const __half* vh_g = g_Vh + (size_t)b*NM*NV;
    const __half* vl_g = g_Vl + (size_t)b*NM*NV;

    // prologue: KV stage 0 via cp.async, then Q tiles via plain ld/st
    {
        load_f16_tile_cp(sb + A_KH, kh_g, NK, 64);
        load_f16_tile_cp(sb + A_KL, kl_g, NK, 64);
        load_f16_tile_cp(sb + A_VH, vh_g, NV, 64);
        load_f16_tile_cp(sb + A_VL, vl_g, NV, 64);
        CP_COMMIT();
    }
    size_t qoff = ((size_t)(b*NH + h)*NN + n0) * NK;
    load_f16_tile((char*)smem + S_QH, g_Qh + qoff, NK, 128);
    load_f16_tile((char*)smem + S_QL, g_Ql + qoff, NK, 128);
    __syncthreads();

    uint32_t qh[4][4];
#pragma unroll
    for (int ks = 0; ks < 4; ks++) ldsm_x4(qh[ks], a_addr(sb + S_QH, wrow0, ks, lane));

    float o[8][4];
#pragma unroll
    for (int j = 0; j < 8; j++) { o[j][0]=0.f; o[j][1]=0.f; o[j][2]=0.f; o[j][3]=0.f; }
    float gmax0 = -1e30f, gmax1 = -1e30f, gs0 = 0.f, gs1 = 0.f;

    const int grow0 = n0 + wrow0 + gid;
    const float* mp0 = mask + (((size_t)(b*NH + h)*NN + grow0))*(size_t)NM + 2*t4;
    const float* mp1 = mp0 + (size_t)8 * NM;

    const int NIT = NM / 64;
    for (int it = 0; it < NIT; it++) {
        const int m0 = it * 64;
        if (it + 1 < NIT) {
            uint32_t st = sb + ((it + 1) & 1) * AST;
            const int m1 = m0 + 64;
            load_f16_tile_cp(st + A_KH, kh_g + (size_t)m1*NK, NK, 64);
            load_f16_tile_cp(st + A_KL, kl_g + (size_t)m1*NK, NK, 64);
            load_f16_tile_cp(st + A_VH, vh_g + (size_t)m1*NV, NV, 64);
            load_f16_tile_cp(st + A_VL, vl_g + (size_t)m1*NV, NV, 64);
            CP_COMMIT();
            CP_WAIT1();
        } else {
            CP_WAIT0();
        }
        __syncthreads();
        const uint32_t st = sb + (it & 1) * AST;

        float c[8][4];
#pragma unroll
        for (int j = 0; j < 8; j++) { c[j][0]=0.f; c[j][1]=0.f; c[j][2]=0.f; c[j][3]=0.f; }
#pragma unroll
        for (int ks = 0; ks < 4; ks++) {
            uint32_t ql[4];
            ldsm_x4(ql, a_addr(sb + S_QL, wrow0, ks, lane));
#pragma unroll
            for (int j = 0; j < 8; j++) {
                uint32_t bh0, bh1, bl0, bl1;
                ldsm_x2(bh0, bh1, b_addr(st + A_KH, j, ks, lane));
                mma16816(c[j], qh[ks], bh0, bh1);
                mma16816(c[j], ql, bh0, bh1);
                ldsm_x2(bl0, bl1, b_addr(st + A_KL, j, ks, lane));
                mma16816(c[j], qh[ks], bl0, bl1);
            }
        }

        float mx0 = -1e30f, mx1 = -1e30f;
#pragma unroll
        for (int j = 0; j < 8; j++) {
            float2 a = *(const float2*)(mp0 + m0 + 8*j);
            float2 d = *(const float2*)(mp1 + m0 + 8*j);
            c[j][0] += a.x; c[j][1] += a.y; c[j][2] += d.x; c[j][3] += d.y;
            mx0 = fmaxf(mx0, fmaxf(c[j][0], c[j][1]));
            mx1 = fmaxf(mx1, fmaxf(c[j][2], c[j][3]));
        }
        mx0 = fmaxf(mx0, __shfl_xor_sync(0xffffffffu, mx0, 1));
        mx0 = fmaxf(mx0, __shfl_xor_sync(0xffffffffu, mx0, 2));
        mx1 = fmaxf(mx1, __shfl_xor_sync(0xffffffffu, mx1, 1));
        mx1 = fmaxf(mx1, __shfl_xor_sync(0xffffffffu, mx1, 2));

        float mn0 = fmaxf(gmax0, mx0), mn1 = fmaxf(gmax1, mx1);
        float sc0 = __expf(gmax0 - mn0), sc1 = __expf(gmax1 - mn1);
        gmax0 = mn0; gmax1 = mn1;

        uint32_t pk[8][2];
        float rs0 = 0.f, rs1 = 0.f;
#pragma unroll
        for (int j = 0; j < 8; j++) {
            __half2 t0 = __floats2half2_rn((c[j][0]-mn0)*L2E, (c[j][1]-mn0)*L2E);
            __half2 t1 = __floats2half2_rn((c[j][2]-mn1)*L2E, (c[j][3]-mn1)*L2E);
            pk[j][0] = ex2_h2(*(uint32_t*)&t0);
            pk[j][1] = ex2_h2(*(uint32_t*)&t1);
            float2 f0 = __half22float2(*(__half2*)&pk[j][0]);
            float2 f1 = __half22float2(*(__half2*)&pk[j][1]);
            rs0 += f0.x + f0.y; rs1 += f1.x + f1.y;
        }
        rs0 += __shfl_xor_sync(0xffffffffu, rs0, 1);
        rs0 += __shfl_xor_sync(0xffffffffu, rs0, 2);
        rs1 += __shfl_xor_sync(0xffffffffu, rs1, 1);
        rs1 += __shfl_xor_sync(0xffffffffu, rs1, 2);
        gs0 = gs0 * sc0 + rs0;
        gs1 = gs1 * sc1 + rs1;

#pragma unroll
        for (int j = 0; j < 8; j++) {
            o[j][0] *= sc0; o[j][1] *= sc0; o[j][2] *= sc1; o[j][3] *= sc1;
        }
#pragma unroll
        for (int ks = 0; ks < 4; ks++) {
            uint32_t pa[4] = { pk[2*ks][0], pk[2*ks][1], pk[2*ks+1][0], pk[2*ks+1][1] };
#pragma unroll
            for (int jv = 0; jv < 8; jv++) {
                uint32_t v0, v1;
                ldsm_x2t(v0, v1, v_addr(st + A_VH, ks, jv, lane));
                mma16816(o[jv], pa, v0, v1);
                ldsm_x2t(v0, v1, v_addr(st + A_VL, ks, jv, lane));
                mma16816(o[jv], pa, v0, v1);
            }
        }
        __syncthreads();
    }

    // epilogue: normalize, split-store O as fp16 hi/lo [b][n][h][v]
    float inv0 = 1.0f / gs0, inv1 = 1.0f / gs1;
    size_t o0 = ((size_t)(b*NN + grow0)*NH + h)*NV + 2*t4;
    size_t o1 = ((size_t)(b*NN + grow0 + 8)*NH + h)*NV + 2*t4;
#pragma unroll
    for (int jv = 0; jv < 8; jv++) {
        split2(o[jv][0]*inv0, o[jv][1]*inv0, &g_Oh[o0 + 8*jv], &g_Ol[o0 + 8*jv]);
        split2(o[jv][2]*inv1, o[jv][3]*inv1, &g_Oh[o1 + 8*jv], &g_Ol[o1 + 8*jv]);
    }
}

// ---------------------------------------------------------------------------
// Kernel 4: output projection. grid (ND/64, NN/128, NB). Contraction = 16 heads.
// ---------------------------------------------------------------------------
__global__ void __launch_bounds__(256, 2)
out_proj_kernel(float* __restrict__ Y) {
    int b = blockIdx.z, n0 = blockIdx.y * 128, d0 = blockIdx.x * 64;
    float c[8][4] = {};
    gemm128x64<false>(g_Oh + (size_t)(b*NN + n0)*(NH*NV), g_Ol + (size_t)(b*NN + n0)*(NH*NV),
                      NH*NV,
                      g_Poh + (size_t)d0*NV, g_Pol + (size_t)d0*NV, NV,
                      (size_t)ND*NV, NH, c);
    int lane = threadIdx.x & 31, w = threadIdx.x >> 5;
    int gid = lane >> 2, t4 = lane & 3;
    int grow0 = n0 + w*16 + gid;
    size_t r0 = (size_t)(b*NN + grow0)*ND + d0;
#pragma unroll
    for (int j = 0; j < 8; j++) {
        int col = 8*j + 2*t4;
        *(float2*)&Y[r0 + col]        = make_float2(c[j][0], c[j][1]);
        *(float2*)&Y[r0 + 8*ND + col] = make_float2(c[j][2], c[j][3]);
    }
}

// ---------------------------------------------------------------------------
extern "C" void kernel_launch(void* const* d_in, const int* in_sizes, int n_in,
                              void* d_out, int out_size) {
    const float* X    = (const float*)d_in[0];
    const float* Mi   = (const float*)d_in[1];
    const float* mask = (const float*)d_in[2];
    const float* Pq   = (const float*)d_in[3];
    const float* Pk   = (const float*)d_in[4];
    const float* Pv   = (const float*)d_in[5];
    const float* Po   = (const float*)d_in[6];
    float* Y = (float*)d_out;

    cudaFuncSetAttribute(q_proj_kernel,   cudaFuncAttributeMaxDynamicSharedMemorySize, SMEM_G);
    cudaFuncSetAttribute(kv_proj_kernel,  cudaFuncAttributeMaxDynamicSharedMemorySize, SMEM_G);
    cudaFuncSetAttribute(attn_kernel,     cudaFuncAttributeMaxDynamicSharedMemorySize, SMEM_ATT);
    cudaFuncSetAttribute(out_proj_kernel, cudaFuncAttributeMaxDynamicSharedMemorySize, SMEM_G);

    __half *xh, *xl, *mh, *ml, *pqh, *pql, *pkh, *pkl, *pvh, *pvl, *poh, *pol;
    cudaGetSymbolAddress((void**)&xh,  g_Xh);  cudaGetSymbolAddress((void**)&xl,  g_Xl);
    cudaGetSymbolAddress((void**)&mh,  g_Mh);  cudaGetSymbolAddress((void**)&ml,  g_Ml);
    cudaGetSymbolAddress((void**)&pqh, g_Pqh); cudaGetSymbolAddress((void**)&pql, g_Pql);
    cudaGetSymbolAddress((void**)&pkh, g_Pkh); cudaGetSymbolAddress((void**)&pkl, g_Pkl);
    cudaGetSymbolAddress((void**)&pvh, g_Pvh); cudaGetSymbolAddress((void**)&pvl, g_Pvl);
    cudaGetSymbolAddress((void**)&poh, g_Poh); cudaGetSymbolAddress((void**)&pol, g_Pol);

    auto split = [&](const float* s, __half* hp, __half* lp, size_t n) {
        int n4 = (int)(n / 4);
        int blocks = (n4 + 255) / 256; if (blocks > 4096) blocks = 4096;
        split_kernel<<<blocks, 256>>>(s, hp, lp, n4);
    };
    split(X,  xh,  xl,  (size_t)NB*NN*ND);
    split(Mi, mh,  ml,  (size_t)NB*NM*ND);
    split(Pq, pqh, pql, (size_t)NH*ND*NK);
    split(Pk, pkh, pkl, (size_t)ND*NK);
    split(Pv, pvh, pvl, (size_t)ND*NV);
    split(Po, poh, pol, (size_t)NH*ND*NV);

    kv_proj_kernel<<<dim3(NM/128, 2, NB), 256, SMEM_G>>>();
    q_proj_kernel<<<dim3(NN/128, NH, NB), 256, SMEM_G>>>();
    attn_kernel<<<dim3(NN/128, NH, NB), 256, SMEM_ATT>>>(mask);
    out_proj_kernel<<<dim3(ND/64, NN/128, NB), 256, SMEM_G>>>(Y);
}

// round 9
// speedup vs baseline: 3.4401x; 1.0200x over previous
#include <cuda_runtime.h>
#include <cuda_fp16.h>
#include <cstdint>

#define NB 2
#define NN 2048
#define NM 2048
#define ND 1024
#define NH 16
#define NK 64
#define NV 64

// ---------------- scratch (__device__ globals; no allocs allowed) ----------
__device__ __half g_Xh[(size_t)NB*NN*ND],   g_Xl[(size_t)NB*NN*ND];
__device__ __half g_Mh[(size_t)NB*NM*ND],   g_Ml[(size_t)NB*NM*ND];
__device__ __half g_Pqh[(size_t)NH*ND*NK],  g_Pql[(size_t)NH*ND*NK];
__device__ __half g_Pkh[(size_t)ND*NK],     g_Pkl[(size_t)ND*NK];
__device__ __half g_Pvh[(size_t)ND*NV],     g_Pvl[(size_t)ND*NV];
__device__ __half g_Poh[(size_t)NH*ND*NV],  g_Pol[(size_t)NH*ND*NV];
__device__ __half g_Qh[(size_t)NB*NH*NN*NK], g_Ql[(size_t)NB*NH*NN*NK];
__device__ __half g_Kh[(size_t)NB*NM*NK],   g_Kl[(size_t)NB*NM*NK];
__device__ __half g_Vh[(size_t)NB*NM*NV],   g_Vl[(size_t)NB*NM*NV];
__device__ __half g_Oh[(size_t)NB*NN*NH*NV], g_Ol[(size_t)NB*NN*NH*NV];

// ---------------- helpers --------------------------------------------------
__device__ __forceinline__ uint32_t smem_u32(const void* p) {
    uint32_t a;
    asm("{ .reg .u64 t; cvta.to.shared.u64 t, %1; cvt.u32.u64 %0, t; }" : "=r"(a) : "l"(p));
    return a;
}
__device__ __forceinline__ void ldsm_x4(uint32_t (&r)[4], uint32_t a) {
    asm volatile("ldmatrix.sync.aligned.m8n8.x4.shared.b16 {%0,%1,%2,%3}, [%4];"
                 : "=r"(r[0]), "=r"(r[1]), "=r"(r[2]), "=r"(r[3]) : "r"(a));
}
__device__ __forceinline__ void ldsm_x4t(uint32_t (&r)[4], uint32_t a) {
    asm volatile("ldmatrix.sync.aligned.m8n8.x4.trans.shared.b16 {%0,%1,%2,%3}, [%4];"
                 : "=r"(r[0]), "=r"(r[1]), "=r"(r[2]), "=r"(r[3]) : "r"(a));
}
__device__ __forceinline__ void mma16816(float (&c)[4], const uint32_t (&a)[4],
                                         uint32_t b0, uint32_t b1) {
    asm volatile("mma.sync.aligned.m16n8k16.row.col.f32.f16.f16.f32 "
                 "{%0,%1,%2,%3}, {%4,%5,%6,%7}, {%8,%9}, {%0,%1,%2,%3};"
                 : "+f"(c[0]), "+f"(c[1]), "+f"(c[2]), "+f"(c[3])
                 : "r"(a[0]), "r"(a[1]), "r"(a[2]), "r"(a[3]), "r"(b0), "r"(b1));
}
__device__ __forceinline__ uint32_t ex2_h2(uint32_t x) {
    uint32_t r;
    asm volatile("ex2.approx.f16x2 %0, %1;" : "=r"(r) : "r"(x));
    return r;
}
__device__ __forceinline__ void split2(float a, float b, __half* hp, __half* lp) {
    __half h0 = __float2half_rn(a), h1 = __float2half_rn(b);
    *(__half2*)hp = __halves2half2(h0, h1);
    *(__half2*)lp = __halves2half2(__float2half_rn(a - __half2float(h0)),
                                   __float2half_rn(b - __half2float(h1)));
}
#define CP_COMMIT() asm volatile("cp.async.commit_group;" ::: "memory")
#define CP_WAIT1()  asm volatile("cp.async.wait_group 1;" ::: "memory")
#define CP_WAIT0()  asm volatile("cp.async.wait_group 0;" ::: "memory")

// swizzled 128B-row f16 tile loader (64 halves per row) — sync version
__device__ __forceinline__ void load_f16_tile(char* s, const __half* g,
                                              int gstride, int rows) {
    for (int i = threadIdx.x; i < rows * 8; i += 256) {
        int row = i >> 3, c = i & 7;
        uint4 v = *(const uint4*)(g + (size_t)row * gstride + c * 8);
        int off = row * 128 + c * 16;
        *(uint4*)(s + (off ^ ((off >> 3) & 0x70))) = v;
    }
}
// cp.async version
__device__ __forceinline__ void load_f16_tile_cp(uint32_t sbase, const __half* g,
                                                 int gstride, int rows) {
    for (int i = threadIdx.x; i < rows * 8; i += 256) {
        int row = i >> 3, c = i & 7;
        int off = row * 128 + c * 16;
        asm volatile("cp.async.cg.shared.global [%0], [%1], 16;"
                     :: "r"(sbase + (off ^ ((off >> 3) & 0x70))),
                        "l"(g + (size_t)row * gstride + c * 8) : "memory");
    }
}
// fragment address helpers (swizzle folded)
__device__ __forceinline__ uint32_t a_addr(uint32_t base, int row0, int ks, int lane) {
    int m = lane >> 3;
    int r = row0 + ((m & 1) << 3) + (lane & 7);
    int cb = ((((m >> 1) << 3) + (ks << 4)) << 1);
    return base + r * 128 + (cb ^ ((r & 7) << 4));
}
// x4 pair: lanes 0-15 -> fragment j, lanes 16-31 -> fragment j+1 (B in [n][k])
__device__ __forceinline__ uint32_t b_addr2(uint32_t base, int j, int ks, int lane) {
    int jj = j + (lane >> 4);
    int l = lane & 15;
    int r = (jj << 3) + (l & 7);
    int cb = (((ks << 4) + ((l >> 3) << 3)) << 1);
    return base + r * 128 + (cb ^ ((l & 7) << 4));
}
// x4 trans pair: lanes 0-15 -> jv, lanes 16-31 -> jv+1 (B in [k][n])
__device__ __forceinline__ uint32_t v_addr2(uint32_t base, int ks, int jv, int lane) {
    int jj = jv + (lane >> 4);
    int l = lane & 15;
    int r = (ks << 4) + l;
    int cb = (jj << 4);
    return base + r * 128 + (cb ^ ((l & 7) << 4));
}

// ---------------------------------------------------------------------------
// Kernel 0: fp32 -> fp16 hi/lo split, ALL tensors in one launch (grid.y = tensor)
// ---------------------------------------------------------------------------
__global__ void split_all_kernel(const float* __restrict__ X, const float* __restrict__ Mi,
                                 const float* __restrict__ Pq, const float* __restrict__ Pk,
                                 const float* __restrict__ Pv, const float* __restrict__ Po) {
    const float* s; __half* hp; __half* lp; size_t n;
    switch (blockIdx.y) {
        case 0: s = X;  hp = g_Xh;  lp = g_Xl;  n = (size_t)NB*NN*ND; break;
        case 1: s = Mi; hp = g_Mh;  lp = g_Ml;  n = (size_t)NB*NM*ND; break;
        case 2: s = Pq; hp = g_Pqh; lp = g_Pql; n = (size_t)NH*ND*NK; break;
        case 3: s = Pk; hp = g_Pkh; lp = g_Pkl; n = (size_t)ND*NK;    break;
        case 4: s = Pv; hp = g_Pvh; lp = g_Pvl; n = (size_t)ND*NV;    break;
        default:s = Po; hp = g_Poh; lp = g_Pol; n = (size_t)NH*ND*NV; break;
    }
    int n4 = (int)(n / 4);
    for (int i = blockIdx.x * blockDim.x + threadIdx.x; i < n4;
         i += gridDim.x * blockDim.x) {
        float4 v = ((const float4*)s)[i];
        split2(v.x, v.y, hp + 4*i,     lp + 4*i);
        split2(v.z, v.w, hp + 4*i + 2, lp + 4*i + 2);
    }
}

// ---------------------------------------------------------------------------
// Shared HMMA core, 2-stage cp.async pipeline, paired x4 B loads.
// ---------------------------------------------------------------------------
#define GST    49152
#define G_SA_H 0
#define G_SA_L 16384
#define G_SB_H 32768
#define G_SB_L 40960
#define SMEM_G 98304

template <bool TB>
__device__ __forceinline__ void gemm128x64(const __half* Ah, const __half* Al, int lda,
                                           const __half* Bh, const __half* Bl, int ldb,
                                           size_t bstep, int nchunks, float (&c)[8][4]) {
    extern __shared__ char smem[];
    uint32_t sb = smem_u32(smem);
    int lane = threadIdx.x & 31, w = threadIdx.x >> 5, wrow0 = w * 16;

    {
        uint32_t st = sb;
        load_f16_tile_cp(st + G_SA_H, Ah, lda, 128);
        load_f16_tile_cp(st + G_SA_L, Al, lda, 128);
        load_f16_tile_cp(st + G_SB_H, Bh, ldb, 64);
        load_f16_tile_cp(st + G_SB_L, Bl, ldb, 64);
        CP_COMMIT();
    }
    for (int ch = 0; ch < nchunks; ch++) {
        if (ch + 1 < nchunks) {
            uint32_t st = sb + ((ch + 1) & 1) * GST;
            load_f16_tile_cp(st + G_SA_H, Ah + (ch + 1) * 64, lda, 128);
            load_f16_tile_cp(st + G_SA_L, Al + (ch + 1) * 64, lda, 128);
            load_f16_tile_cp(st + G_SB_H, Bh + (ch + 1) * bstep, ldb, 64);
            load_f16_tile_cp(st + G_SB_L, Bl + (ch + 1) * bstep, ldb, 64);
            CP_COMMIT();
            CP_WAIT1();
        } else {
            CP_WAIT0();
        }
        __syncthreads();
        uint32_t st = sb + (ch & 1) * GST;
#pragma unroll
        for (int ks = 0; ks < 4; ks++) {
            uint32_t ah[4], al[4];
            ldsm_x4(ah, a_addr(st + G_SA_H, wrow0, ks, lane));
            ldsm_x4(al, a_addr(st + G_SA_L, wrow0, ks, lane));
#pragma unroll
            for (int j = 0; j < 8; j += 2) {
                uint32_t bh[4], bl[4];
                if (TB) {
                    ldsm_x4t(bh, v_addr2(st + G_SB_H, ks, j, lane));
                    ldsm_x4t(bl, v_addr2(st + G_SB_L, ks, j, lane));
                } else {
                    ldsm_x4(bh, b_addr2(st + G_SB_H, j, ks, lane));
                    ldsm_x4(bl, b_addr2(st + G_SB_L, j, ks, lane));
                }
                mma16816(c[j],   ah, bh[0], bh[1]);
                mma16816(c[j],   al, bh[0], bh[1]);
                mma16816(c[j],   ah, bl[0], bl[1]);
                mma16816(c[j+1], ah, bh[2], bh[3]);
                mma16816(c[j+1], al, bh[2], bh[3]);
                mma16816(c[j+1], ah, bl[2], bl[3]);
            }
        }
        __syncthreads();
    }
}

// ---------------------------------------------------------------------------
// Kernel 1: Q projection. grid (NN/128, NH, NB)
// ---------------------------------------------------------------------------
__global__ void __launch_bounds__(256, 2)
q_proj_kernel() {
    int b = blockIdx.z, h = blockIdx.y, n0 = blockIdx.x * 128;
    float c[8][4] = {};
    gemm128x64<true>(g_Xh + (size_t)(b*NN + n0)*ND, g_Xl + (size_t)(b*NN + n0)*ND, ND,
                     g_Pqh + (size_t)h*ND*NK, g_Pql + (size_t)h*ND*NK, NK,
                     (size_t)64*NK, ND/64, c);
    int lane = threadIdx.x & 31, w = threadIdx.x >> 5;
    int gid = lane >> 2, t4 = lane & 3;
    int grow0 = n0 + w*16 + gid;
    size_t r0 = ((size_t)(b*NH + h)*NN + grow0)*NK;
#pragma unroll
    for (int j = 0; j < 8; j++) {
        int col = 8*j + 2*t4;
        split2(c[j][0], c[j][1], &g_Qh[r0 + col], &g_Ql[r0 + col]);
        split2(c[j][2], c[j][3], &g_Qh[r0 + 8*NK + col], &g_Ql[r0 + 8*NK + col]);
    }
}

// ---------------------------------------------------------------------------
// Kernel 2: K/V projection. grid (NM/128, 2(sel), NB)
// ---------------------------------------------------------------------------
__global__ void __launch_bounds__(256, 2)
kv_proj_kernel() {
    int b = blockIdx.z, sel = blockIdx.y, m0 = blockIdx.x * 128;
    const __half* Bh = sel ? g_Pvh : g_Pkh;
    const __half* Bl = sel ? g_Pvl : g_Pkl;
    float c[8][4] = {};
    gemm128x64<true>(g_Mh + (size_t)(b*NM + m0)*ND, g_Ml + (size_t)(b*NM + m0)*ND, ND,
                     Bh, Bl, NK, (size_t)64*NK, ND/64, c);
    __half* Ch = sel ? g_Vh : g_Kh;
    __half* Cl = sel ? g_Vl : g_Kl;
    int lane = threadIdx.x & 31, w = threadIdx.x >> 5;
    int gid = lane >> 2, t4 = lane & 3;
    int grow0 = m0 + w*16 + gid;
    size_t r0 = (size_t)(b*NM + grow0)*NK;
#pragma unroll
    for (int j = 0; j < 8; j++) {
        int col = 8*j + 2*t4;
        split2(c[j][0], c[j][1], &Ch[r0 + col], &Cl[r0 + col]);
        split2(c[j][2], c[j][3], &Ch[r0 + 8*NK + col], &Cl[r0 + 8*NK + col]);
    }
}

// ---------------------------------------------------------------------------
// Kernel 3: mma.sync flash attention, 2-stage cp.async K/V pipeline,
// paired x4 B loads.
// ---------------------------------------------------------------------------
#define AST    32768
#define A_KH   0
#define A_KL   8192
#define A_VH   16384
#define A_VL   24576
#define S_QH   65536
#define S_QL   81920
#define SMEM_ATT 98304
#define L2E 1.4426950408889634f

__global__ void __launch_bounds__(256, 2)
attn_kernel(const float* __restrict__ mask) {
    extern __shared__ char smem[];
    const uint32_t sb = smem_u32(smem);
    const int tid = threadIdx.x;
    const int w = tid >> 5, lane = tid & 31;
    const int gid = lane >> 2, t4 = lane & 3;
    const int wrow0 = w * 16;
    const int b = blockIdx.z, h = blockIdx.y, n0 = blockIdx.x * 128;

    const __half* kh_g = g_Kh + (size_t)b*NM*NK;
    const __half* kl_g = g_Kl + (size_t)b*NM*NK;
    const __half* vh_g = g_Vh + (size_t)b*NM*NV;
    const __half* vl_g = g_Vl + (size_t)b*NM*NV;

    {
        load_f16_tile_cp(sb + A_KH, kh_g, NK, 64);
        load_f16_tile_cp(sb + A_KL, kl_g, NK, 64);
        load_f16_tile_cp(sb + A_VH, vh_g, NV, 64);
        load_f16_tile_cp(sb + A_VL, vl_g, NV, 64);
        CP_COMMIT();
    }
    size_t qoff = ((size_t)(b*NH + h)*NN + n0) * NK;
    load_f16_tile((char*)smem + S_QH, g_Qh + qoff, NK, 128);
    load_f16_tile((char*)smem + S_QL, g_Ql + qoff, NK, 128);
    __syncthreads();

    uint32_t qh[4][4];
#pragma unroll
    for (int ks = 0; ks < 4; ks++) ldsm_x4(qh[ks], a_addr(sb + S_QH, wrow0, ks, lane));

    float o[8][4];
#pragma unroll
    for (int j = 0; j < 8; j++) { o[j][0]=0.f; o[j][1]=0.f; o[j][2]=0.f; o[j][3]=0.f; }
    float gmax0 = -1e30f, gmax1 = -1e30f, gs0 = 0.f, gs1 = 0.f;

    const int grow0 = n0 + wrow0 + gid;
    const float* mp0 = mask + (((size_t)(b*NH + h)*NN + grow0))*(size_t)NM + 2*t4;
    const float* mp1 = mp0 + (size_t)8 * NM;

    const int NIT = NM / 64;
    for (int it = 0; it < NIT; it++) {
        const int m0 = it * 64;
        if (it + 1 < NIT) {
            uint32_t st = sb + ((it + 1) & 1) * AST;
            const int m1 = m0 + 64;
            load_f16_tile_cp(st + A_KH, kh_g + (size_t)m1*NK, NK, 64);
            load_f16_tile_cp(st + A_KL, kl_g + (size_t)m1*NK, NK, 64);
            load_f16_tile_cp(st + A_VH, vh_g + (size_t)m1*NV, NV, 64);
            load_f16_tile_cp(st + A_VL, vl_g + (size_t)m1*NV, NV, 64);
            CP_COMMIT();
            CP_WAIT1();
        } else {
            CP_WAIT0();
        }
        __syncthreads();
        const uint32_t st = sb + (it & 1) * AST;

        float c[8][4];
#pragma unroll
        for (int j = 0; j < 8; j++) { c[j][0]=0.f; c[j][1]=0.f; c[j][2]=0.f; c[j][3]=0.f; }
#pragma unroll
        for (int ks = 0; ks < 4; ks++) {
            uint32_t ql[4];
            ldsm_x4(ql, a_addr(sb + S_QL, wrow0, ks, lane));
#pragma unroll
            for (int j = 0; j < 8; j += 2) {
                uint32_t bh[4], bl[4];
                ldsm_x4(bh, b_addr2(st + A_KH, j, ks, lane));
                ldsm_x4(bl, b_addr2(st + A_KL, j, ks, lane));
                mma16816(c[j],   qh[ks], bh[0], bh[1]);
                mma16816(c[j],   ql,     bh[0], bh[1]);
                mma16816(c[j],   qh[ks], bl[0], bl[1]);
                mma16816(c[j+1], qh[ks], bh[2], bh[3]);
                mma16816(c[j+1], ql,     bh[2], bh[3]);
                mma16816(c[j+1], qh[ks], bl[2], bl[3]);
            }
        }

        float mx0 = -1e30f, mx1 = -1e30f;
#pragma unroll
        for (int j = 0; j < 8; j++) {
            float2 a = *(const float2*)(mp0 + m0 + 8*j);
            float2 d = *(const float2*)(mp1 + m0 + 8*j);
            c[j][0] += a.x; c[j][1] += a.y; c[j][2] += d.x; c[j][3] += d.y;
            mx0 = fmaxf(mx0, fmaxf(c[j][0], c[j][1]));
            mx1 = fmaxf(mx1, fmaxf(c[j][2], c[j][3]));
        }
        mx0 = fmaxf(mx0, __shfl_xor_sync(0xffffffffu, mx0, 1));
        mx0 = fmaxf(mx0, __shfl_xor_sync(0xffffffffu, mx0, 2));
        mx1 = fmaxf(mx1, __shfl_xor_sync(0xffffffffu, mx1, 1));
        mx1 = fmaxf(mx1, __shfl_xor_sync(0xffffffffu, mx1, 2));

        float mn0 = fmaxf(gmax0, mx0), mn1 = fmaxf(gmax1, mx1);
        float sc0 = __expf(gmax0 - mn0), sc1 = __expf(gmax1 - mn1);
        gmax0 = mn0; gmax1 = mn1;

        uint32_t pk[8][2];
        float rs0 = 0.f, rs1 = 0.f;
#pragma unroll
        for (int j = 0; j < 8; j++) {
            __half2 t0 = __floats2half2_rn((c[j][0]-mn0)*L2E, (c[j][1]-mn0)*L2E);
            __half2 t1 = __floats2half2_rn((c[j][2]-mn1)*L2E, (c[j][3]-mn1)*L2E);
            pk[j][0] = ex2_h2(*(uint32_t*)&t0);
            pk[j][1] = ex2_h2(*(uint32_t*)&t1);
            float2 f0 = __half22float2(*(__half2*)&pk[j][0]);
            float2 f1 = __half22float2(*(__half2*)&pk[j][1]);
            rs0 += f0.x + f0.y; rs1 += f1.x + f1.y;
        }
        rs0 += __shfl_xor_sync(0xffffffffu, rs0, 1);
        rs0 += __shfl_xor_sync(0xffffffffu, rs0, 2);
        rs1 += __shfl_xor_sync(0xffffffffu, rs1, 1);
        rs1 += __shfl_xor_sync(0xffffffffu, rs1, 2);
        gs0 = gs0 * sc0 + rs0;
        gs1 = gs1 * sc1 + rs1;

#pragma unroll
        for (int j = 0; j < 8; j++) {
            o[j][0] *= sc0; o[j][1] *= sc0; o[j][2] *= sc1; o[j][3] *= sc1;
        }
#pragma unroll
        for (int ks = 0; ks < 4; ks++) {
            uint32_t pa[4] = { pk[2*ks][0], pk[2*ks][1], pk[2*ks+1][0], pk[2*ks+1][1] };
#pragma unroll
            for (int jv = 0; jv < 8; jv += 2) {
                uint32_t vh[4], vl[4];
                ldsm_x4t(vh, v_addr2(st + A_VH, ks, jv, lane));
                ldsm_x4t(vl, v_addr2(st + A_VL, ks, jv, lane));
                mma16816(o[jv],   pa, vh[0], vh[1]);
                mma16816(o[jv],   pa, vl[0], vl[1]);
                mma16816(o[jv+1], pa, vh[2], vh[3]);
                mma16816(o[jv+1], pa, vl[2], vl[3]);
            }
        }
        __syncthreads();
    }

    // epilogue: normalize, split-store O as fp16 hi/lo [b][n][h][v]
    float inv0 = 1.0f / gs0, inv1 = 1.0f / gs1;
    size_t o0 = ((size_t)(b*NN + grow0)*NH + h)*NV + 2*t4;
    size_t o1 = ((size_t)(b*NN + grow0 + 8)*NH + h)*NV + 2*t4;
#pragma unroll
    for (int jv = 0; jv < 8; jv++) {
        split2(o[jv][0]*inv0, o[jv][1]*inv0, &g_Oh[o0 + 8*jv], &g_Ol[o0 + 8*jv]);
        split2(o[jv][2]*inv1, o[jv][3]*inv1, &g_Oh[o1 + 8*jv], &g_Ol[o1 + 8*jv]);
    }
}

// ---------------------------------------------------------------------------
// Kernel 4: output projection. grid (ND/64, NN/128, NB). Contraction = 16 heads.
// ---------------------------------------------------------------------------
__global__ void __launch_bounds__(256, 2)
out_proj_kernel(float* __restrict__ Y) {
    int b = blockIdx.z, n0 = blockIdx.y * 128, d0 = blockIdx.x * 64;
    float c[8][4] = {};
    gemm128x64<false>(g_Oh + (size_t)(b*NN + n0)*(NH*NV), g_Ol + (size_t)(b*NN + n0)*(NH*NV),
                      NH*NV,
                      g_Poh + (size_t)d0*NV, g_Pol + (size_t)d0*NV, NV,
                      (size_t)ND*NV, NH, c);
    int lane = threadIdx.x & 31, w = threadIdx.x >> 5;
    int gid = lane >> 2, t4 = lane & 3;
    int grow0 = n0 + w*16 + gid;
    size_t r0 = (size_t)(b*NN + grow0)*ND + d0;
#pragma unroll
    for (int j = 0; j < 8; j++) {
        int col = 8*j + 2*t4;
        *(float2*)&Y[r0 + col]        = make_float2(c[j][0], c[j][1]);
        *(float2*)&Y[r0 + 8*ND + col] = make_float2(c[j][2], c[j][3]);
    }
}

// ---------------------------------------------------------------------------
extern "C" void kernel_launch(void* const* d_in, const int* in_sizes, int n_in,
                              void* d_out, int out_size) {
    const float* X    = (const float*)d_in[0];
    const float* Mi   = (const float*)d_in[1];
    const float* mask = (const float*)d_in[2];
    const float* Pq   = (const float*)d_in[3];
    const float* Pk   = (const float*)d_in[4];
    const float* Pv   = (const float*)d_in[5];
    const float* Po   = (const float*)d_in[6];
    float* Y = (float*)d_out;

    cudaFuncSetAttribute(q_proj_kernel,   cudaFuncAttributeMaxDynamicSharedMemorySize, SMEM_G);
    cudaFuncSetAttribute(kv_proj_kernel,  cudaFuncAttributeMaxDynamicSharedMemorySize, SMEM_G);
    cudaFuncSetAttribute(attn_kernel,     cudaFuncAttributeMaxDynamicSharedMemorySize, SMEM_ATT);
    cudaFuncSetAttribute(out_proj_kernel, cudaFuncAttributeMaxDynamicSharedMemorySize, SMEM_G);

    split_all_kernel<<<dim3(2048, 6), 256>>>(X, Mi, Pq, Pk, Pv, Po);

    kv_proj_kernel<<<dim3(NM/128, 2, NB), 256, SMEM_G>>>();
    q_proj_kernel<<<dim3(NN/128, NH, NB), 256, SMEM_G>>>();
    attn_kernel<<<dim3(NN/128, NH, NB), 256, SMEM_ATT>>>(mask);
    out_proj_kernel<<<dim3(ND/64, NN/128, NB), 256, SMEM_G>>>(Y);
}

// round 10
// speedup vs baseline: 3.8446x; 1.1176x over previous
#include <cuda_runtime.h>
#include <cuda_fp16.h>
#include <cstdint>

#define NB 2
#define NN 2048
#define NM 2048
#define ND 1024
#define NH 16
#define NK 64
#define NV 64

// ---------------- scratch (__device__ globals; no allocs allowed) ----------
__device__ __half g_Xh[(size_t)NB*NN*ND],   g_Xl[(size_t)NB*NN*ND];
__device__ __half g_Mh[(size_t)NB*NM*ND],   g_Ml[(size_t)NB*NM*ND];
__device__ __half g_Pqh[(size_t)NH*ND*NK],  g_Pql[(size_t)NH*ND*NK];
__device__ __half g_Pkh[(size_t)ND*NK],     g_Pkl[(size_t)ND*NK];
__device__ __half g_Pvh[(size_t)ND*NV],     g_Pvl[(size_t)ND*NV];
__device__ __half g_Poh[(size_t)NH*ND*NV],  g_Pol[(size_t)NH*ND*NV];
__device__ __half g_Qh[(size_t)NB*NH*NN*NK], g_Ql[(size_t)NB*NH*NN*NK];
__device__ __half g_Kh[(size_t)NB*NM*NK],   g_Kl[(size_t)NB*NM*NK];
__device__ __half g_Vh[(size_t)NB*NM*NV],   g_Vl[(size_t)NB*NM*NV];
__device__ __half g_Oh[(size_t)NB*NN*NH*NV], g_Ol[(size_t)NB*NN*NH*NV];

// ---------------- helpers --------------------------------------------------
__device__ __forceinline__ uint32_t smem_u32(const void* p) {
    uint32_t a;
    asm("{ .reg .u64 t; cvta.to.shared.u64 t, %1; cvt.u32.u64 %0, t; }" : "=r"(a) : "l"(p));
    return a;
}
__device__ __forceinline__ void ldsm_x4(uint32_t (&r)[4], uint32_t a) {
    asm volatile("ldmatrix.sync.aligned.m8n8.x4.shared.b16 {%0,%1,%2,%3}, [%4];"
                 : "=r"(r[0]), "=r"(r[1]), "=r"(r[2]), "=r"(r[3]) : "r"(a));
}
__device__ __forceinline__ void ldsm_x4t(uint32_t (&r)[4], uint32_t a) {
    asm volatile("ldmatrix.sync.aligned.m8n8.x4.trans.shared.b16 {%0,%1,%2,%3}, [%4];"
                 : "=r"(r[0]), "=r"(r[1]), "=r"(r[2]), "=r"(r[3]) : "r"(a));
}
__device__ __forceinline__ void mma16816(float (&c)[4], const uint32_t (&a)[4],
                                         uint32_t b0, uint32_t b1) {
    asm volatile("mma.sync.aligned.m16n8k16.row.col.f32.f16.f16.f32 "
                 "{%0,%1,%2,%3}, {%4,%5,%6,%7}, {%8,%9}, {%0,%1,%2,%3};"
                 : "+f"(c[0]), "+f"(c[1]), "+f"(c[2]), "+f"(c[3])
                 : "r"(a[0]), "r"(a[1]), "r"(a[2]), "r"(a[3]), "r"(b0), "r"(b1));
}
__device__ __forceinline__ uint32_t ex2_h2(uint32_t x) {
    uint32_t r;
    asm volatile("ex2.approx.f16x2 %0, %1;" : "=r"(r) : "r"(x));
    return r;
}
__device__ __forceinline__ void split2(float a, float b, __half* hp, __half* lp) {
    __half h0 = __float2half_rn(a), h1 = __float2half_rn(b);
    *(__half2*)hp = __halves2half2(h0, h1);
    *(__half2*)lp = __halves2half2(__float2half_rn(a - __half2float(h0)),
                                   __float2half_rn(b - __half2float(h1)));
}
#define CP_COMMIT() asm volatile("cp.async.commit_group;" ::: "memory")
#define CP_WAIT1()  asm volatile("cp.async.wait_group 1;" ::: "memory")
#define CP_WAIT0()  asm volatile("cp.async.wait_group 0;" ::: "memory")
#define PF_L2(p)    asm volatile("prefetch.global.L2 [%0];" :: "l"(p))

// swizzled 128B-row f16 tile loader (64 halves per row) — sync version
__device__ __forceinline__ void load_f16_tile(char* s, const __half* g,
                                              int gstride, int rows) {
    for (int i = threadIdx.x; i < rows * 8; i += 256) {
        int row = i >> 3, c = i & 7;
        uint4 v = *(const uint4*)(g + (size_t)row * gstride + c * 8);
        int off = row * 128 + c * 16;
        *(uint4*)(s + (off ^ ((off >> 3) & 0x70))) = v;
    }
}
// cp.async version
__device__ __forceinline__ void load_f16_tile_cp(uint32_t sbase, const __half* g,
                                                 int gstride, int rows) {
    for (int i = threadIdx.x; i < rows * 8; i += 256) {
        int row = i >> 3, c = i & 7;
        int off = row * 128 + c * 16;
        asm volatile("cp.async.cg.shared.global [%0], [%1], 16;"
                     :: "r"(sbase + (off ^ ((off >> 3) & 0x70))),
                        "l"(g + (size_t)row * gstride + c * 8) : "memory");
    }
}
// fragment address helpers (swizzle folded)
__device__ __forceinline__ uint32_t a_addr(uint32_t base, int row0, int ks, int lane) {
    int m = lane >> 3;
    int r = row0 + ((m & 1) << 3) + (lane & 7);
    int cb = ((((m >> 1) << 3) + (ks << 4)) << 1);
    return base + r * 128 + (cb ^ ((r & 7) << 4));
}
// x4 pair: lanes 0-15 -> fragment j, lanes 16-31 -> fragment j+1 (B in [n][k])
__device__ __forceinline__ uint32_t b_addr2(uint32_t base, int j, int ks, int lane) {
    int jj = j + (lane >> 4);
    int l = lane & 15;
    int r = (jj << 3) + (l & 7);
    int cb = (((ks << 4) + ((l >> 3) << 3)) << 1);
    return base + r * 128 + (cb ^ ((l & 7) << 4));
}
// x4 trans pair: lanes 0-15 -> jv, lanes 16-31 -> jv+1 (B in [k][n])
__device__ __forceinline__ uint32_t v_addr2(uint32_t base, int ks, int jv, int lane) {
    int jj = jv + (lane >> 4);
    int l = lane & 15;
    int r = (ks << 4) + l;
    int cb = (jj << 4);
    return base + r * 128 + (cb ^ ((l & 7) << 4));
}

// ---------------------------------------------------------------------------
// Kernel 0: fp32 -> fp16 hi/lo split, ALL tensors in one launch (grid.y = tensor)
// ---------------------------------------------------------------------------
__global__ void split_all_kernel(const float* __restrict__ X, const float* __restrict__ Mi,
                                 const float* __restrict__ Pq, const float* __restrict__ Pk,
                                 const float* __restrict__ Pv, const float* __restrict__ Po) {
    const float* s; __half* hp; __half* lp; size_t n;
    switch (blockIdx.y) {
        case 0: s = X;  hp = g_Xh;  lp = g_Xl;  n = (size_t)NB*NN*ND; break;
        case 1: s = Mi; hp = g_Mh;  lp = g_Ml;  n = (size_t)NB*NM*ND; break;
        case 2: s = Pq; hp = g_Pqh; lp = g_Pql; n = (size_t)NH*ND*NK; break;
        case 3: s = Pk; hp = g_Pkh; lp = g_Pkl; n = (size_t)ND*NK;    break;
        case 4: s = Pv; hp = g_Pvh; lp = g_Pvl; n = (size_t)ND*NV;    break;
        default:s = Po; hp = g_Poh; lp = g_Pol; n = (size_t)NH*ND*NV; break;
    }
    int n4 = (int)(n / 4);
    for (int i = blockIdx.x * blockDim.x + threadIdx.x; i < n4;
         i += gridDim.x * blockDim.x) {
        float4 v = ((const float4*)s)[i];
        split2(v.x, v.y, hp + 4*i,     lp + 4*i);
        split2(v.z, v.w, hp + 4*i + 2, lp + 4*i + 2);
    }
}

// ---------------------------------------------------------------------------
// Shared HMMA core, 2-stage cp.async pipeline, paired x4 B loads.
// ---------------------------------------------------------------------------
#define GST    49152
#define G_SA_H 0
#define G_SA_L 16384
#define G_SB_H 32768
#define G_SB_L 40960
#define SMEM_G 98304

template <bool TB>
__device__ __forceinline__ void gemm128x64(const __half* Ah, const __half* Al, int lda,
                                           const __half* Bh, const __half* Bl, int ldb,
                                           size_t bstep, int nchunks, float (&c)[8][4]) {
    extern __shared__ char smem[];
    uint32_t sb = smem_u32(smem);
    int lane = threadIdx.x & 31, w = threadIdx.x >> 5, wrow0 = w * 16;

    {
        uint32_t st = sb;
        load_f16_tile_cp(st + G_SA_H, Ah, lda, 128);
        load_f16_tile_cp(st + G_SA_L, Al, lda, 128);
        load_f16_tile_cp(st + G_SB_H, Bh, ldb, 64);
        load_f16_tile_cp(st + G_SB_L, Bl, ldb, 64);
        CP_COMMIT();
    }
    for (int ch = 0; ch < nchunks; ch++) {
        if (ch + 1 < nchunks) {
            uint32_t st = sb + ((ch + 1) & 1) * GST;
            load_f16_tile_cp(st + G_SA_H, Ah + (ch + 1) * 64, lda, 128);
            load_f16_tile_cp(st + G_SA_L, Al + (ch + 1) * 64, lda, 128);
            load_f16_tile_cp(st + G_SB_H, Bh + (ch + 1) * bstep, ldb, 64);
            load_f16_tile_cp(st + G_SB_L, Bl + (ch + 1) * bstep, ldb, 64);
            CP_COMMIT();
            CP_WAIT1();
        } else {
            CP_WAIT0();
        }
        __syncthreads();
        uint32_t st = sb + (ch & 1) * GST;
#pragma unroll
        for (int ks = 0; ks < 4; ks++) {
            uint32_t ah[4], al[4];
            ldsm_x4(ah, a_addr(st + G_SA_H, wrow0, ks, lane));
            ldsm_x4(al, a_addr(st + G_SA_L, wrow0, ks, lane));
#pragma unroll
            for (int j = 0; j < 8; j += 2) {
                uint32_t bh[4], bl[4];
                if (TB) {
                    ldsm_x4t(bh, v_addr2(st + G_SB_H, ks, j, lane));
                    ldsm_x4t(bl, v_addr2(st + G_SB_L, ks, j, lane));
                } else {
                    ldsm_x4(bh, b_addr2(st + G_SB_H, j, ks, lane));
                    ldsm_x4(bl, b_addr2(st + G_SB_L, j, ks, lane));
                }
                mma16816(c[j],   ah, bh[0], bh[1]);
                mma16816(c[j],   al, bh[0], bh[1]);
                mma16816(c[j],   ah, bl[0], bl[1]);
                mma16816(c[j+1], ah, bh[2], bh[3]);
                mma16816(c[j+1], al, bh[2], bh[3]);
                mma16816(c[j+1], ah, bl[2], bl[3]);
            }
        }
        __syncthreads();
    }
}

// ---------------------------------------------------------------------------
// Kernel 1: Q projection. grid (NN/128, NH, NB)
// ---------------------------------------------------------------------------
__global__ void __launch_bounds__(256, 2)
q_proj_kernel() {
    int b = blockIdx.z, h = blockIdx.y, n0 = blockIdx.x * 128;
    float c[8][4] = {};
    gemm128x64<true>(g_Xh + (size_t)(b*NN + n0)*ND, g_Xl + (size_t)(b*NN + n0)*ND, ND,
                     g_Pqh + (size_t)h*ND*NK, g_Pql + (size_t)h*ND*NK, NK,
                     (size_t)64*NK, ND/64, c);
    int lane = threadIdx.x & 31, w = threadIdx.x >> 5;
    int gid = lane >> 2, t4 = lane & 3;
    int grow0 = n0 + w*16 + gid;
    size_t r0 = ((size_t)(b*NH + h)*NN + grow0)*NK;
#pragma unroll
    for (int j = 0; j < 8; j++) {
        int col = 8*j + 2*t4;
        split2(c[j][0], c[j][1], &g_Qh[r0 + col], &g_Ql[r0 + col]);
        split2(c[j][2], c[j][3], &g_Qh[r0 + 8*NK + col], &g_Ql[r0 + 8*NK + col]);
    }
}

// ---------------------------------------------------------------------------
// Kernel 2: K/V projection. grid (NM/128, 2(sel), NB)
// ---------------------------------------------------------------------------
__global__ void __launch_bounds__(256, 2)
kv_proj_kernel() {
    int b = blockIdx.z, sel = blockIdx.y, m0 = blockIdx.x * 128;
    const __half* Bh = sel ? g_Pvh : g_Pkh;
    const __half* Bl = sel ? g_Pvl : g_Pkl;
    float c[8][4] = {};
    gemm128x64<true>(g_Mh + (size_t)(b*NM + m0)*ND, g_Ml + (size_t)(b*NM + m0)*ND, ND,
                     Bh, Bl, NK, (size_t)64*NK, ND/64, c);
    __half* Ch = sel ? g_Vh : g_Kh;
    __half* Cl = sel ? g_Vl : g_Kl;
    int lane = threadIdx.x & 31, w = threadIdx.x >> 5;
    int gid = lane >> 2, t4 = lane & 3;
    int grow0 = m0 + w*16 + gid;
    size_t r0 = (size_t)(b*NM + grow0)*NK;
#pragma unroll
    for (int j = 0; j < 8; j++) {
        int col = 8*j + 2*t4;
        split2(c[j][0], c[j][1], &Ch[r0 + col], &Cl[r0 + col]);
        split2(c[j][2], c[j][3], &Ch[r0 + 8*NK + col], &Cl[r0 + 8*NK + col]);
    }
}

// ---------------------------------------------------------------------------
// Kernel 3: mma.sync flash attention, 2-stage cp.async K/V pipeline,
// paired x4 B loads, L2 mask prefetch, V-hi-only PV.
// Stage (24KB): KH 0, KL 8K, VH 16K; stages at 0, 24K. Q at 48K/64K. 80KB.
// ---------------------------------------------------------------------------
#define AST    24576
#define A_KH   0
#define A_KL   8192
#define A_VH   16384
#define S_QH   49152
#define S_QL   65536
#define SMEM_ATT 81920
#define L2E 1.4426950408889634f

__global__ void __launch_bounds__(256, 2)
attn_kernel(const float* __restrict__ mask) {
    extern __shared__ char smem[];
    const uint32_t sb = smem_u32(smem);
    const int tid = threadIdx.x;
    const int w = tid >> 5, lane = tid & 31;
    const int gid = lane >> 2, t4 = lane & 3;
    const int wrow0 = w * 16;
    const int b = blockIdx.z, h = blockIdx.y, n0 = blockIdx.x * 128;

    const __half* kh_g = g_Kh + (size_t)b*NM*NK;
    const __half* kl_g = g_Kl + (size_t)b*NM*NK;
    const __half* vh_g = g_Vh + (size_t)b*NM*NV;

    // per-lane mask prefetch pointer: 32 lanes cover this warp's 16 rows x 64 cols
    const float* pfb = mask + ((size_t)(b*NH + h)*NN + n0 + wrow0 + (lane >> 1))*(size_t)NM
                            + (lane & 1) * 32;

    {
        load_f16_tile_cp(sb + A_KH, kh_g, NK, 64);
        load_f16_tile_cp(sb + A_KL, kl_g, NK, 64);
        load_f16_tile_cp(sb + A_VH, vh_g, NV, 64);
        CP_COMMIT();
        PF_L2(pfb);                       // iter-0 mask into L2
    }
    size_t qoff = ((size_t)(b*NH + h)*NN + n0) * NK;
    load_f16_tile((char*)smem + S_QH, g_Qh + qoff, NK, 128);
    load_f16_tile((char*)smem + S_QL, g_Ql + qoff, NK, 128);
    __syncthreads();

    uint32_t qh[4][4];
#pragma unroll
    for (int ks = 0; ks < 4; ks++) ldsm_x4(qh[ks], a_addr(sb + S_QH, wrow0, ks, lane));

    float o[8][4];
#pragma unroll
    for (int j = 0; j < 8; j++) { o[j][0]=0.f; o[j][1]=0.f; o[j][2]=0.f; o[j][3]=0.f; }
    float gmax0 = -1e30f, gmax1 = -1e30f, gs0 = 0.f, gs1 = 0.f;

    const int grow0 = n0 + wrow0 + gid;
    const float* mp0 = mask + (((size_t)(b*NH + h)*NN + grow0))*(size_t)NM + 2*t4;
    const float* mp1 = mp0 + (size_t)8 * NM;

    const int NIT = NM / 64;
    for (int it = 0; it < NIT; it++) {
        const int m0 = it * 64;
        if (it + 1 < NIT) {
            uint32_t st = sb + ((it + 1) & 1) * AST;
            const int m1 = m0 + 64;
            load_f16_tile_cp(st + A_KH, kh_g + (size_t)m1*NK, NK, 64);
            load_f16_tile_cp(st + A_KL, kl_g + (size_t)m1*NK, NK, 64);
            load_f16_tile_cp(st + A_VH, vh_g + (size_t)m1*NV, NV, 64);
            CP_COMMIT();
            PF_L2(pfb + m1);              // next iter's mask into L2
            CP_WAIT1();
        } else {
            CP_WAIT0();
        }
        __syncthreads();
        const uint32_t st = sb + (it & 1) * AST;

        float c[8][4];
#pragma unroll
        for (int j = 0; j < 8; j++) { c[j][0]=0.f; c[j][1]=0.f; c[j][2]=0.f; c[j][3]=0.f; }
#pragma unroll
        for (int ks = 0; ks < 4; ks++) {
            uint32_t ql[4];
            ldsm_x4(ql, a_addr(sb + S_QL, wrow0, ks, lane));
#pragma unroll
            for (int j = 0; j < 8; j += 2) {
                uint32_t bh[4], bl[4];
                ldsm_x4(bh, b_addr2(st + A_KH, j, ks, lane));
                ldsm_x4(bl, b_addr2(st + A_KL, j, ks, lane));
                mma16816(c[j],   qh[ks], bh[0], bh[1]);
                mma16816(c[j],   ql,     bh[0], bh[1]);
                mma16816(c[j],   qh[ks], bl[0], bl[1]);
                mma16816(c[j+1], qh[ks], bh[2], bh[3]);
                mma16816(c[j+1], ql,     bh[2], bh[3]);
                mma16816(c[j+1], qh[ks], bl[2], bl[3]);
            }
        }

        float mx0 = -1e30f, mx1 = -1e30f;
#pragma unroll
        for (int j = 0; j < 8; j++) {
            float2 a = *(const float2*)(mp0 + m0 + 8*j);
            float2 d = *(const float2*)(mp1 + m0 + 8*j);
            c[j][0] += a.x; c[j][1] += a.y; c[j][2] += d.x; c[j][3] += d.y;
            mx0 = fmaxf(mx0, fmaxf(c[j][0], c[j][1]));
            mx1 = fmaxf(mx1, fmaxf(c[j][2], c[j][3]));
        }
        mx0 = fmaxf(mx0, __shfl_xor_sync(0xffffffffu, mx0, 1));
        mx0 = fmaxf(mx0, __shfl_xor_sync(0xffffffffu, mx0, 2));
        mx1 = fmaxf(mx1, __shfl_xor_sync(0xffffffffu, mx1, 1));
        mx1 = fmaxf(mx1, __shfl_xor_sync(0xffffffffu, mx1, 2));

        float mn0 = fmaxf(gmax0, mx0), mn1 = fmaxf(gmax1, mx1);
        float sc0 = __expf(gmax0 - mn0), sc1 = __expf(gmax1 - mn1);
        gmax0 = mn0; gmax1 = mn1;

        uint32_t pk[8][2];
        float rs0 = 0.f, rs1 = 0.f;
#pragma unroll
        for (int j = 0; j < 8; j++) {
            __half2 t0 = __floats2half2_rn((c[j][0]-mn0)*L2E, (c[j][1]-mn0)*L2E);
            __half2 t1 = __floats2half2_rn((c[j][2]-mn1)*L2E, (c[j][3]-mn1)*L2E);
            pk[j][0] = ex2_h2(*(uint32_t*)&t0);
            pk[j][1] = ex2_h2(*(uint32_t*)&t1);
            float2 f0 = __half22float2(*(__half2*)&pk[j][0]);
            float2 f1 = __half22float2(*(__half2*)&pk[j][1]);
            rs0 += f0.x + f0.y; rs1 += f1.x + f1.y;
        }
        rs0 += __shfl_xor_sync(0xffffffffu, rs0, 1);
        rs0 += __shfl_xor_sync(0xffffffffu, rs0, 2);
        rs1 += __shfl_xor_sync(0xffffffffu, rs1, 1);
        rs1 += __shfl_xor_sync(0xffffffffu, rs1, 2);
        gs0 = gs0 * sc0 + rs0;
        gs1 = gs1 * sc1 + rs1;

#pragma unroll
        for (int j = 0; j < 8; j++) {
            o[j][0] *= sc0; o[j][1] *= sc0; o[j][2] *= sc1; o[j][3] *= sc1;
        }
#pragma unroll
        for (int ks = 0; ks < 4; ks++) {
            uint32_t pa[4] = { pk[2*ks][0], pk[2*ks][1], pk[2*ks+1][0], pk[2*ks+1][1] };
#pragma unroll
            for (int jv = 0; jv < 8; jv += 2) {
                uint32_t vh[4];
                ldsm_x4t(vh, v_addr2(st + A_VH, ks, jv, lane));
                mma16816(o[jv],   pa, vh[0], vh[1]);
                mma16816(o[jv+1], pa, vh[2], vh[3]);
            }
        }
        __syncthreads();
    }

    // epilogue: normalize, split-store O as fp16 hi/lo [b][n][h][v]
    float inv0 = 1.0f / gs0, inv1 = 1.0f / gs1;
    size_t o0 = ((size_t)(b*NN + grow0)*NH + h)*NV + 2*t4;
    size_t o1 = ((size_t)(b*NN + grow0 + 8)*NH + h)*NV + 2*t4;
#pragma unroll
    for (int jv = 0; jv < 8; jv++) {
        split2(o[jv][0]*inv0, o[jv][1]*inv0, &g_Oh[o0 + 8*jv], &g_Ol[o0 + 8*jv]);
        split2(o[jv][2]*inv1, o[jv][3]*inv1, &g_Oh[o1 + 8*jv], &g_Ol[o1 + 8*jv]);
    }
}

// ---------------------------------------------------------------------------
// Kernel 4: output projection. grid (ND/64, NN/128, NB). Contraction = 16 heads.
// ---------------------------------------------------------------------------
__global__ void __launch_bounds__(256, 2)
out_proj_kernel(float* __restrict__ Y) {
    int b = blockIdx.z, n0 = blockIdx.y * 128, d0 = blockIdx.x * 64;
    float c[8][4] = {};
    gemm128x64<false>(g_Oh + (size_t)(b*NN + n0)*(NH*NV), g_Ol + (size_t)(b*NN + n0)*(NH*NV),
                      NH*NV,
                      g_Poh + (size_t)d0*NV, g_Pol + (size_t)d0*NV, NV,
                      (size_t)ND*NV, NH, c);
    int lane = threadIdx.x & 31, w = threadIdx.x >> 5;
    int gid = lane >> 2, t4 = lane & 3;
    int grow0 = n0 + w*16 + gid;
    size_t r0 = (size_t)(b*NN + grow0)*ND + d0;
#pragma unroll
    for (int j = 0; j < 8; j++) {
        int col = 8*j + 2*t4;
        *(float2*)&Y[r0 + col]        = make_float2(c[j][0], c[j][1]);
        *(float2*)&Y[r0 + 8*ND + col] = make_float2(c[j][2], c[j][3]);
    }
}

// ---------------------------------------------------------------------------
extern "C" void kernel_launch(void* const* d_in, const int* in_sizes, int n_in,
                              void* d_out, int out_size) {
    const float* X    = (const float*)d_in[0];
    const float* Mi   = (const float*)d_in[1];
    const float* mask = (const float*)d_in[2];
    const float* Pq   = (const float*)d_in[3];
    const float* Pk   = (const float*)d_in[4];
    const float* Pv   = (const float*)d_in[5];
    const float* Po   = (const float*)d_in[6];
    float* Y = (float*)d_out;

    cudaFuncSetAttribute(q_proj_kernel,   cudaFuncAttributeMaxDynamicSharedMemorySize, SMEM_G);
    cudaFuncSetAttribute(kv_proj_kernel,  cudaFuncAttributeMaxDynamicSharedMemorySize, SMEM_G);
    cudaFuncSetAttribute(attn_kernel,     cudaFuncAttributeMaxDynamicSharedMemorySize, SMEM_ATT);
    cudaFuncSetAttribute(out_proj_kernel, cudaFuncAttributeMaxDynamicSharedMemorySize, SMEM_G);

    split_all_kernel<<<dim3(2048, 6), 256>>>(X, Mi, Pq, Pk, Pv, Po);

    kv_proj_kernel<<<dim3(NM/128, 2, NB), 256, SMEM_G>>>();
    q_proj_kernel<<<dim3(NN/128, NH, NB), 256, SMEM_G>>>();
    attn_kernel<<<dim3(NN/128, NH, NB), 256, SMEM_ATT>>>(mask);
    out_proj_kernel<<<dim3(ND/64, NN/128, NB), 256, SMEM_G>>>(Y);
}